// round 13
// baseline (speedup 1.0000x reference)
#include <cuda_runtime.h>
#include <cuda_bf16.h>
#include <math.h>
#include <stdint.h>

#define B   16
#define C   512
#define NSP 1024
#define NH  4
#define DH  128
#define NG  8
#define SC2 (0.08838834764831845f * 1.4426950408889634f)   // scale * log2(e)

// All GEMM operands stored as pre-swizzled 16KB panels: [128 rows][128 bytes],
// byte-in-row = (col*2) ^ ((row&7)*16).

// ---------------- scratch ----------------
__device__ __nv_bfloat16 g_xnh[(size_t)B*NSP*C];     // [b][kc=8][rt=8] panels
__device__ __nv_bfloat16 g_xnl[(size_t)B*NSP*C];
__device__ __nv_bfloat16 g_qwh[(size_t)3*C*C];       // [kc=8][nt=12] panels
__device__ __nv_bfloat16 g_qwl[(size_t)3*C*C];
__device__ __nv_bfloat16 g_pwh[(size_t)C*C];         // [kc=8][rt=4] panels
__device__ __nv_bfloat16 g_pwl[(size_t)C*C];
__device__ __nv_bfloat16 g_Qh [(size_t)B*NSP*C];     // [b][h][qb=8][kcp=2] panels (scale folded)
__device__ __nv_bfloat16 g_Ql [(size_t)B*NSP*C];
__device__ __nv_bfloat16 g_atth[(size_t)B*NSP*C];    // [b][kc=8][nt=8] panels
__device__ __nv_bfloat16 g_attl[(size_t)B*NSP*C];
__device__ __nv_bfloat16 g_Kh[(size_t)B*NH*NSP*DH];  // [bh][chunk=8][kcp=2] panels
__device__ __nv_bfloat16 g_Kl[(size_t)B*NH*NSP*DH];
__device__ __nv_bfloat16 g_Vh[(size_t)B*NH*NSP*DH];  // [bh][chunk=8][tokp=2] panels (d-rows)
__device__ __nv_bfloat16 g_Vl[(size_t)B*NH*NSP*DH];

// ---------------- helpers ----------------
__device__ __forceinline__ uint32_t smem_u32(const void* p) {
    uint32_t a;
    asm("{ .reg .u64 t; cvta.to.shared.u64 t, %1; cvt.u32.u64 %0, t; }" : "=r"(a) : "l"(p));
    return a;
}
__device__ __forceinline__ void ldsm4(uint32_t* r, uint32_t a) {
    asm volatile("ldmatrix.sync.aligned.m8n8.x4.shared.b16 {%0,%1,%2,%3}, [%4];"
        : "=r"(r[0]), "=r"(r[1]), "=r"(r[2]), "=r"(r[3]) : "r"(a));
}
__device__ __forceinline__ void mma16816(float* d, const uint32_t* a, uint32_t b0, uint32_t b1) {
    asm volatile("mma.sync.aligned.m16n8k16.row.col.f32.bf16.bf16.f32 "
        "{%0,%1,%2,%3}, {%4,%5,%6,%7}, {%8,%9}, {%0,%1,%2,%3};"
        : "+f"(d[0]), "+f"(d[1]), "+f"(d[2]), "+f"(d[3])
        : "r"(a[0]), "r"(a[1]), "r"(a[2]), "r"(a[3]), "r"(b0), "r"(b1));
}
__device__ __forceinline__ uint32_t pk2(float lo, float hi) {
    uint32_t r;
    asm("cvt.rn.bf16x2.f32 %0, %1, %2;" : "=r"(r) : "f"(hi), "f"(lo));
    return r;
}
__device__ __forceinline__ float lo16f(uint32_t u) { return __uint_as_float(u << 16); }
__device__ __forceinline__ float hi16f(uint32_t u) { return __uint_as_float(u & 0xFFFF0000u); }

#define MBAR_INIT(a, cnt) asm volatile("mbarrier.init.shared.b64 [%0], %1;" :: "r"(a), "r"((uint32_t)(cnt)) : "memory")
#define MBAR_EXPECT(a, bytes) asm volatile("mbarrier.arrive.expect_tx.shared.b64 _, [%0], %1;" :: "r"(a), "r"((uint32_t)(bytes)) : "memory")
#define MBAR_WAIT(a, par) do { \
    uint32_t _m = (a); uint32_t _p = (par); uint32_t _d; \
    asm volatile("{\n\t.reg .pred p;\n\tmbarrier.try_wait.parity.acquire.cta.shared::cta.b64 p, [%1], %2;\n\tselp.b32 %0, 1, 0, p;\n\t}" \
        : "=r"(_d) : "r"(_m), "r"(_p) : "memory"); \
    if (!_d) { \
        asm volatile("{\n\t.reg .pred P1;\n\tWL_%=:\n\tmbarrier.try_wait.parity.acquire.cta.shared::cta.b64 P1, [%0], %1, 0x989680;\n\t@P1 bra.uni WD_%=;\n\tbra.uni WL_%=;\n\tWD_%=:\n\t}" \
            :: "r"(_m), "r"(_p) : "memory"); \
    } } while (0)
#define BULK_G2S(dst, src, bytes, mbar) \
    asm volatile("cp.async.bulk.shared::cluster.global.mbarrier::complete_tx::bytes [%0], [%1], %2, [%3];" \
        :: "r"(dst), "l"(src), "r"((uint32_t)(bytes)), "r"(mbar) : "memory")

// ---------------- weight convert -> swizzled panels ----------------
__global__ __launch_bounds__(256) void wcvt_kernel(const float* __restrict__ src,
    __nv_bfloat16* __restrict__ dh, __nv_bfloat16* __restrict__ dl, int O, int tiles)
{
    int i2 = blockIdx.x * 256 + threadIdx.x;
    if (i2 * 2 >= O * C) return;
    int o = (i2 * 2) / C, c = (i2 * 2) % C;
    float v0 = src[(size_t)o * C + c];
    float v1 = src[(size_t)o * C + c + 1];
    __nv_bfloat16 h0 = __float2bfloat16(v0), h1 = __float2bfloat16(v1);
    uint32_t ph = (uint32_t)__bfloat16_as_ushort(h0) | ((uint32_t)__bfloat16_as_ushort(h1) << 16);
    __nv_bfloat16 l0 = __float2bfloat16(v0 - __bfloat162float(h0));
    __nv_bfloat16 l1 = __float2bfloat16(v1 - __bfloat162float(h1));
    uint32_t pl = (uint32_t)__bfloat16_as_ushort(l0) | ((uint32_t)__bfloat16_as_ushort(l1) << 16);
    int panel = (c >> 6) * tiles + (o >> 7);
    int row = o & 127;
    uint32_t off = (uint32_t)panel * 16384u + (uint32_t)row * 128u
                 + ((uint32_t)((c & 63) * 2) ^ (uint32_t)((row & 7) * 16));
    *(uint32_t*)((char*)dh + off) = ph;
    *(uint32_t*)((char*)dl + off) = pl;
}

// ---------------- GroupNorm -> swizzled xn panels [b][kc][rt] ----------------
__global__ __launch_bounds__(256) void gn_t_kernel(
    const float* __restrict__ x, const float* __restrict__ gamma,
    const float* __restrict__ beta,
    __nv_bfloat16* __restrict__ xnh, __nv_bfloat16* __restrict__ xnl)
{
    const int CG = C / NG;
    const int GE = CG * NSP;
    int b = blockIdx.x / NG, g = blockIdx.x % NG;
    const float* xp = x + ((size_t)b * C + (size_t)g * CG) * NSP;
    int t = threadIdx.x;

    float s = 0.f, s2 = 0.f;
    for (int i = t; i < GE; i += 256) { float v = xp[i]; s += v; s2 += v * v; }
    __shared__ float rs[256], rs2[256];
    rs[t] = s; rs2[t] = s2;
    __syncthreads();
    for (int st = 128; st > 0; st >>= 1) {
        if (t < st) { rs[t] += rs[t + st]; rs2[t] += rs2[t + st]; }
        __syncthreads();
    }
    float mu  = rs[0] * (1.f / GE);
    float var = rs2[0] * (1.f / GE) - mu * mu;
    float inv = rsqrtf(var + 1e-5f);

    __shared__ float tile[8][32][33];
    int warp = t >> 5, lane = t & 31;
    for (int tt = warp; tt < 64; tt += 8) {
        int ci = tt >> 5, ni = tt & 31;
        for (int i = 0; i < 32; i++) {
            int c = ci * 32 + i;
            int cg2 = g * CG + c;
            float v = xp[(size_t)c * NSP + ni * 32 + lane];
            tile[warp][i][lane] = (v - mu) * inv * gamma[cg2] + beta[cg2];
        }
        __syncwarp();
        int col = ci * 32 + lane;
        for (int i = 0; i < 32; i++) {
            int n = ni * 32 + i;
            int rt = n >> 7, row = n & 127;
            float v = tile[warp][lane][i];
            __nv_bfloat16 h = __float2bfloat16(v);
            size_t pb = (((size_t)b * 8 + g) * 8 + rt) * 16384;
            uint32_t off = (uint32_t)row * 128u
                         + ((uint32_t)(col * 2) ^ (uint32_t)((row & 7) * 16));
            *(__nv_bfloat16*)((char*)xnh + pb + off) = h;
            *(__nv_bfloat16*)((char*)xnl + pb + off) = __float2bfloat16(v - __bfloat162float(h));
        }
        __syncwarp();
    }
}

// ---------------- GEMM mainloop: 256x128 CTA, 512 thr (16 warps, 32x64 warp tiles) ----------------
#define ST_AL 32768u
#define ST_BH 65536u
#define ST_BL 81920u
#define ST_SZ 98304u

__device__ __forceinline__ void issue_chunk(uint32_t sdst, uint32_t mbar,
    const char* Ah, const char* Al, size_t aoff,
    const char* Bh, const char* Bl, size_t boff)
{
    MBAR_EXPECT(mbar, 98304u);
    BULK_G2S(sdst,         Ah + aoff, 32768u, mbar);
    BULK_G2S(sdst + ST_AL, Al + aoff, 32768u, mbar);
    BULK_G2S(sdst + ST_BH, Bh + boff, 16384u, mbar);
    BULK_G2S(sdst + ST_BL, Bl + boff, 16384u, mbar);
}

__device__ __forceinline__ void gemm_mainloop(uint32_t sbase, uint32_t mb0, uint32_t mb1,
    const char* Ah, const char* Al, int rtA, int RT,
    const char* Bh, const char* Bl, int ntB, int NT,
    int nk, float (&acc)[2][8][4])
{
    const int tid = threadIdx.x, lane = tid & 31, wid = tid >> 5;
    const int warp_m = (wid >> 1) * 32;
    const int warp_n = (wid & 1) * 64;
    const int lr = (lane & 7) + 8 * ((lane >> 3) & 1);
    const int lc = 16 * (lane >> 4);
    const uint32_t rx = (uint32_t)(lr & 7) * 16u;
    uint32_t kx[4];
#pragma unroll
    for (int k = 0; k < 4; k++)
        kx[k] = ((32u * k) ^ (rx & 0x60u)) + ((uint32_t)lc ^ (rx & 0x10u));

    uint32_t rA[2], rB[4];
#pragma unroll
    for (int t = 0; t < 2; t++) {
        int full = warp_m + t * 16 + lr;
        rA[t] = (uint32_t)((full >> 7) * 16384 + (full & 127) * 128);
    }
#pragma unroll
    for (int t = 0; t < 4; t++)
        rB[t] = (uint32_t)(warp_n + t * 16 + lr) * 128u;

    if (tid == 0) {
        issue_chunk(sbase, mb0, Ah, Al, (size_t)(0 * RT + rtA) * 16384,
                    Bh, Bl, (size_t)(0 * NT + ntB) * 16384);
        if (nk > 1)
            issue_chunk(sbase + ST_SZ, mb1, Ah, Al, (size_t)(1 * RT + rtA) * 16384,
                        Bh, Bl, (size_t)(1 * NT + ntB) * 16384);
    }

    for (int i = 0; i < nk; i++) {
        MBAR_WAIT((i & 1) ? mb1 : mb0, (uint32_t)((i >> 1) & 1));

        uint32_t bufA = sbase + (uint32_t)(i & 1) * ST_SZ;
        uint32_t bufB = bufA + ST_BH;
#pragma unroll
        for (int kk = 0; kk < 4; kk++) {
            uint32_t kof = kx[kk];
            uint32_t ah0[4], ah1[4], al0[4], al1[4];
            ldsm4(ah0, bufA + rA[0] + kof);
            ldsm4(ah1, bufA + rA[1] + kof);
            ldsm4(al0, bufA + ST_AL + rA[0] + kof);
            ldsm4(al1, bufA + ST_AL + rA[1] + kof);
#pragma unroll
            for (int nt = 0; nt < 4; nt++) {
                uint32_t bh_[4], bl_[4];
                ldsm4(bh_, bufB + rB[nt] + kof);
                ldsm4(bl_, bufB + 16384u + rB[nt] + kof);
#pragma unroll
                for (int t = 0; t < 2; t++) {
                    int j = nt * 2 + t;
                    uint32_t b0 = bh_[t], b1 = bh_[t + 2];
                    uint32_t c0 = bl_[t], c1 = bl_[t + 2];
                    mma16816(acc[0][j], ah0, b0, b1);
                    mma16816(acc[1][j], ah1, b0, b1);
                    mma16816(acc[0][j], al0, b0, b1);
                    mma16816(acc[1][j], al1, b0, b1);
                    mma16816(acc[0][j], ah0, c0, c1);
                    mma16816(acc[1][j], ah1, c0, c1);
                }
            }
        }
        __syncthreads();
        if (tid == 0 && i + 2 < nk)
            issue_chunk(sbase + (uint32_t)(i & 1) * ST_SZ, (i & 1) ? mb1 : mb0,
                        Ah, Al, (size_t)((i + 2) * RT + rtA) * 16384,
                        Bh, Bl, (size_t)((i + 2) * NT + ntB) * 16384);
    }
}

// ---------------- QKV GEMM with fused Q/K/V panel epilogues ----------------
__global__ __launch_bounds__(512) void gemm_qkv(
    const __nv_bfloat16* __restrict__ xnh, const __nv_bfloat16* __restrict__ xnl,
    const __nv_bfloat16* __restrict__ qwh, const __nv_bfloat16* __restrict__ qwl,
    const float* __restrict__ bias,
    __nv_bfloat16* __restrict__ Qh, __nv_bfloat16* __restrict__ Ql,
    __nv_bfloat16* __restrict__ Kh, __nv_bfloat16* __restrict__ Kl,
    __nv_bfloat16* __restrict__ Vh, __nv_bfloat16* __restrict__ Vl)
{
    extern __shared__ char dsm[];
    char* base = (char*)((((uintptr_t)dsm) + 1023) & ~(uintptr_t)1023);
    const uint32_t sbase = smem_u32(base);
    __shared__ __align__(8) unsigned long long smb[2];
    uint32_t mb0 = smem_u32(&smb[0]), mb1 = smem_u32(&smb[1]);
    const int tid = threadIdx.x, lane = tid & 31, wid = tid >> 5;
    const int bb = blockIdx.z;
    const int nb = blockIdx.x;
    const int m0 = blockIdx.y * 256, n0 = nb * 128;

    if (tid == 0) { MBAR_INIT(mb0, 1); MBAR_INIT(mb1, 1); }
    __syncthreads();

    float acc[2][8][4] = {};
    gemm_mainloop(sbase, mb0, mb1,
        (const char*)xnh + (size_t)bb * NSP * C * 2,
        (const char*)xnl + (size_t)bb * NSP * C * 2, m0 >> 7, 8,
        (const char*)qwh, (const char*)qwl, nb, 12, 8, acc);

    const int warp_m = (wid >> 1) * 32;
    const int warp_n = (wid & 1) * 64;
    const int er = lane >> 2, ec = (lane & 3) * 2;

    if (nb < 4) {
        int h = nb;
#pragma unroll
        for (int mt = 0; mt < 2; mt++)
#pragma unroll
        for (int half = 0; half < 2; half++) {
            int m = m0 + warp_m + mt * 16 + er + half * 8;
            int qb = m >> 7, row = m & 127;
            size_t pb = (((size_t)(bb * NH + h) * 8 + qb) * 2) * 16384;
            uint32_t rowoff = (uint32_t)row * 128u;
            uint32_t rsw = (uint32_t)((row & 7) * 16);
#pragma unroll
            for (int j = 0; j < 8; j++) {
                int n = n0 + warp_n + j * 8 + ec;
                int cl = n & 127;
                float v0 = (acc[mt][j][half * 2 + 0] + bias[n])     * SC2;
                float v1 = (acc[mt][j][half * 2 + 1] + bias[n + 1]) * SC2;
                uint32_t ph = pk2(v0, v1);
                uint32_t pl = pk2(v0 - lo16f(ph), v1 - hi16f(ph));
                size_t off = pb + (size_t)(cl >> 6) * 16384 + rowoff
                           + (((uint32_t)((cl & 63) * 2)) ^ rsw);
                *(uint32_t*)((char*)Qh + off) = ph;
                *(uint32_t*)((char*)Ql + off) = pl;
            }
        }
    } else if (nb < 8) {
        int h = nb - 4;
        size_t pbase = (size_t)(bb * NH + h) * 8 * 32768;
#pragma unroll
        for (int mt = 0; mt < 2; mt++)
#pragma unroll
        for (int half = 0; half < 2; half++) {
            int m = m0 + warp_m + mt * 16 + er + half * 8;
            int mc = m >> 7, row = m & 127;
            size_t cb = pbase + (size_t)mc * 32768;
            uint32_t rowoff = (uint32_t)row * 128u;
            uint32_t rsw = (uint32_t)((row & 7) * 16);
#pragma unroll
            for (int j = 0; j < 8; j++) {
                int dloc = warp_n + j * 8 + ec;
                int n = n0 + dloc;
                float v0 = acc[mt][j][half * 2 + 0] + bias[n];
                float v1 = acc[mt][j][half * 2 + 1] + bias[n + 1];
                uint32_t ph = pk2(v0, v1);
                uint32_t pl = pk2(v0 - lo16f(ph), v1 - hi16f(ph));
                size_t off = cb + (size_t)(dloc >> 6) * 16384 + rowoff
                           + (((uint32_t)((dloc & 63) * 2)) ^ rsw);
                *(uint32_t*)((char*)Kh + off) = ph;
                *(uint32_t*)((char*)Kl + off) = pl;
            }
        }
    } else {
        int h = nb - 8;
        float* vt = (float*)base;
#pragma unroll
        for (int mt = 0; mt < 2; mt++)
#pragma unroll
        for (int half = 0; half < 2; half++) {
            int mloc = warp_m + mt * 16 + er + half * 8;
#pragma unroll
            for (int j = 0; j < 8; j++) {
                int dloc = warp_n + j * 8 + ec;
                int n = n0 + dloc;
                vt[mloc * 129 + dloc]     = acc[mt][j][half * 2 + 0] + bias[n];
                vt[mloc * 129 + dloc + 1] = acc[mt][j][half * 2 + 1] + bias[n + 1];
            }
        }
        __syncthreads();
        size_t pbase = (size_t)(bb * NH + h) * 8 * 32768;
        for (int idx = tid; idx < 16384; idx += 512) {
            int cLoc = idx >> 13;
            int rem = idx & 8191;
            int o2 = rem * 2;
            int p = o2 >> 13, rem2 = o2 & 8191;
            int d = rem2 >> 6, kvc = rem2 & 63;
            int srow = cLoc * 128 + p * 64 + kvc;
            float v0 = vt[srow * 129 + d];
            float v1 = vt[(srow + 1) * 129 + d];
            uint32_t ph = pk2(v0, v1);
            uint32_t pl = pk2(v0 - lo16f(ph), v1 - hi16f(ph));
            size_t off = pbase + (size_t)((m0 >> 7) + cLoc) * 32768
                       + (size_t)p * 16384 + (uint32_t)d * 128u
                       + (((uint32_t)(kvc * 2)) ^ (uint32_t)((d & 7) * 16));
            *(uint32_t*)((char*)Vh + off) = ph;
            *(uint32_t*)((char*)Vl + off) = pl;
        }
    }
}

// ---------------- generic GEMM (proj) ----------------
__global__ __launch_bounds__(512) void gemm_bf(
    const __nv_bfloat16* __restrict__ Ah, const __nv_bfloat16* __restrict__ Al, int RT,
    const __nv_bfloat16* __restrict__ Bh, const __nv_bfloat16* __restrict__ Bl, int NT,
    long long sBb,
    float* __restrict__ Cm, long long ldc, long long sCb,
    const float* __restrict__ bias_m,
    const float* __restrict__ res, long long ldr, long long sRb)
{
    extern __shared__ char dsm[];
    char* base = (char*)((((uintptr_t)dsm) + 1023) & ~(uintptr_t)1023);
    const uint32_t sbase = smem_u32(base);
    __shared__ __align__(8) unsigned long long smb[2];
    uint32_t mb0 = smem_u32(&smb[0]), mb1 = smem_u32(&smb[1]);
    const int tid = threadIdx.x, lane = tid & 31, wid = tid >> 5;
    const int bb = blockIdx.z;
    const int m0 = blockIdx.y * 256, n0 = blockIdx.x * 128;

    if (tid == 0) { MBAR_INIT(mb0, 1); MBAR_INIT(mb1, 1); }
    __syncthreads();

    float acc[2][8][4] = {};
    gemm_mainloop(sbase, mb0, mb1,
        (const char*)Ah, (const char*)Al, m0 >> 7, RT,
        (const char*)Bh + (size_t)bb * sBb, (const char*)Bl + (size_t)bb * sBb,
        n0 >> 7, NT, 8, acc);

    Cm += (size_t)bb * sCb;
    if (res) res += (size_t)bb * sRb;
    const int warp_m = (wid >> 1) * 32, warp_n = (wid & 1) * 64;
    const int er = lane >> 2, ec = (lane & 3) * 2;
#pragma unroll
    for (int mt = 0; mt < 2; mt++)
#pragma unroll
    for (int half = 0; half < 2; half++) {
        int m = m0 + warp_m + mt * 16 + er + half * 8;
        float bm_ = bias_m ? bias_m[m] : 0.f;
#pragma unroll
        for (int j = 0; j < 8; j++) {
            int n = n0 + warp_n + j * 8 + ec;
            float v0 = acc[mt][j][half * 2 + 0] + bm_;
            float v1 = acc[mt][j][half * 2 + 1] + bm_;
            if (res) { const float* rp = res + (size_t)m * ldr + n; v0 += rp[0]; v1 += rp[1]; }
            *(float2*)&Cm[(size_t)m * ldc + n] = make_float2(v0, v1);
        }
    }
}

// ---------------- fused flash attention v2: Q in registers, K double-buffered ----------------
// smem: KBUF0 @0 (64KB), KBUF1 @64K, VBUF @128K. Each buf: hi 32KB | lo 32KB.
#define FKB0 0u
#define FKB1 65536u
#define FVB  131072u

__global__ __launch_bounds__(256) void flash_kernel(
    const __nv_bfloat16* __restrict__ Qh, const __nv_bfloat16* __restrict__ Ql,
    const __nv_bfloat16* __restrict__ Kh, const __nv_bfloat16* __restrict__ Kl,
    const __nv_bfloat16* __restrict__ Vh, const __nv_bfloat16* __restrict__ Vl,
    __nv_bfloat16* __restrict__ atth, __nv_bfloat16* __restrict__ attl)
{
    extern __shared__ char dsm[];
    char* base = (char*)((((uintptr_t)dsm) + 1023) & ~(uintptr_t)1023);
    const uint32_t sb = smem_u32(base);
    __shared__ __align__(8) unsigned long long fmb[3];
    uint32_t mbK0 = smem_u32(&fmb[0]), mbK1 = smem_u32(&fmb[1]), mbV = smem_u32(&fmb[2]);
    const int tid = threadIdx.x, lane = tid & 31, wid = tid >> 5;
    const int qb = blockIdx.x;
    const int z = blockIdx.y;
    const int b = z >> 2, h = z & 3;

    const char* KhP = (const char*)Kh + (size_t)z * 8 * 32768;
    const char* KlP = (const char*)Kl + (size_t)z * 8 * 32768;
    const char* VhP = (const char*)Vh + (size_t)z * 8 * 32768;
    const char* VlP = (const char*)Vl + (size_t)z * 8 * 32768;
    const char* QhP = (const char*)Qh + (size_t)((b * NH + h) * 8 + qb) * 32768;
    const char* QlP = (const char*)Ql + (size_t)((b * NH + h) * 8 + qb) * 32768;

    if (tid == 0) { MBAR_INIT(mbK0, 1); MBAR_INIT(mbK1, 1); MBAR_INIT(mbV, 1); }
    __syncthreads();

    // stage Q through KBUF0, load to registers
    if (tid == 0) {
        MBAR_EXPECT(mbK0, 65536u);
        BULK_G2S(sb + FKB0,          QhP, 32768u, mbK0);
        BULK_G2S(sb + FKB0 + 32768u, QlP, 32768u, mbK0);
    }

    const int lr = (lane & 7) + 8 * ((lane >> 3) & 1);
    const int lc = 16 * (lane >> 4);
    const uint32_t rx = (uint32_t)(lr & 7) * 16u;
    uint32_t kx[4];
#pragma unroll
    for (int k = 0; k < 4; k++)
        kx[k] = ((32u * k) ^ (rx & 0x60u)) + ((uint32_t)lc ^ (rx & 0x10u));
    const uint32_t qoff = (uint32_t)(16 * wid + lr) * 128u;

    uint32_t qh[2][4][4], ql[2][4][4];
    MBAR_WAIT(mbK0, 0u);
#pragma unroll
    for (int p = 0; p < 2; p++)
#pragma unroll
    for (int kk = 0; kk < 4; kk++) {
        uint32_t qa = sb + FKB0 + p * 16384 + qoff + kx[kk];
        ldsm4(qh[p][kk], qa);
        ldsm4(ql[p][kk], qa + 32768u);
    }
    __syncthreads();

    // prime pipeline: K0 -> KBUF0, K1 -> KBUF1, V0 -> VBUF
    if (tid == 0) {
        MBAR_EXPECT(mbK0, 65536u);
        BULK_G2S(sb + FKB0,          KhP, 32768u, mbK0);
        BULK_G2S(sb + FKB0 + 32768u, KlP, 32768u, mbK0);
        MBAR_EXPECT(mbK1, 65536u);
        BULK_G2S(sb + FKB1,          KhP + 32768, 32768u, mbK1);
        BULK_G2S(sb + FKB1 + 32768u, KlP + 32768, 32768u, mbK1);
        MBAR_EXPECT(mbV, 65536u);
        BULK_G2S(sb + FVB,          VhP, 32768u, mbV);
        BULK_G2S(sb + FVB + 32768u, VlP, 32768u, mbV);
    }

    float accO[16][4] = {};
    float M0 = -1e30f, M1 = -1e30f, L0 = 0.f, L1 = 0.f;

    for (int c = 0; c < 8; c++) {
        float accS[16][4] = {};
        uint32_t kb = sb + ((c & 1) ? FKB1 : FKB0);
        uint32_t kpar = (c & 1) ? (uint32_t)((c >> 1) & 1) : (uint32_t)(((c >> 1) & 1) ^ 1);
        MBAR_WAIT((c & 1) ? mbK1 : mbK0, kpar);
        // ---- QK (Q from registers) ----
#pragma unroll
        for (int p = 0; p < 2; p++) {
#pragma unroll
            for (int kk = 0; kk < 4; kk++) {
                uint32_t kof = kx[kk];
#pragma unroll
                for (int nt = 0; nt < 8; nt++) {
                    uint32_t ka = kb + p * 16384 + (uint32_t)(nt * 16 + lr) * 128u + kof;
                    uint32_t bh_[4], bl_[4];
                    ldsm4(bh_, ka); ldsm4(bl_, ka + 32768u);
                    mma16816(accS[2*nt],   qh[p][kk], bh_[0], bh_[2]);
                    mma16816(accS[2*nt],   ql[p][kk], bh_[0], bh_[2]);
                    mma16816(accS[2*nt],   qh[p][kk], bl_[0], bl_[2]);
                    mma16816(accS[2*nt+1], qh[p][kk], bh_[1], bh_[3]);
                    mma16816(accS[2*nt+1], ql[p][kk], bh_[1], bh_[3]);
                    mma16816(accS[2*nt+1], qh[p][kk], bl_[1], bl_[3]);
                }
            }
        }
        __syncthreads();
        if (tid == 0 && c + 2 < 8) {
            uint32_t mk = (c & 1) ? mbK1 : mbK0;
            MBAR_EXPECT(mk, 65536u);
            BULK_G2S(kb,           KhP + (size_t)(c + 2) * 32768, 32768u, mk);
            BULK_G2S(kb + 32768u,  KlP + (size_t)(c + 2) * 32768, 32768u, mk);
        }
        // ---- online softmax (base-2) ----
        float m0 = -1e30f, m1 = -1e30f;
#pragma unroll
        for (int j = 0; j < 16; j++) {
            m0 = fmaxf(m0, fmaxf(accS[j][0], accS[j][1]));
            m1 = fmaxf(m1, fmaxf(accS[j][2], accS[j][3]));
        }
        m0 = fmaxf(m0, __shfl_xor_sync(0xffffffffu, m0, 1));
        m0 = fmaxf(m0, __shfl_xor_sync(0xffffffffu, m0, 2));
        m1 = fmaxf(m1, __shfl_xor_sync(0xffffffffu, m1, 1));
        m1 = fmaxf(m1, __shfl_xor_sync(0xffffffffu, m1, 2));
        float nM0 = fmaxf(M0, m0), nM1 = fmaxf(M1, m1);
        float a0 = exp2f(M0 - nM0), a1 = exp2f(M1 - nM1);
        M0 = nM0; M1 = nM1;
        float s0 = 0.f, s1 = 0.f;
#pragma unroll
        for (int j = 0; j < 16; j++) {
            accS[j][0] = exp2f(accS[j][0] - M0);
            accS[j][1] = exp2f(accS[j][1] - M0);
            accS[j][2] = exp2f(accS[j][2] - M1);
            accS[j][3] = exp2f(accS[j][3] - M1);
            s0 += accS[j][0] + accS[j][1];
            s1 += accS[j][2] + accS[j][3];
        }
        s0 += __shfl_xor_sync(0xffffffffu, s0, 1);
        s0 += __shfl_xor_sync(0xffffffffu, s0, 2);
        s1 += __shfl_xor_sync(0xffffffffu, s1, 1);
        s1 += __shfl_xor_sync(0xffffffffu, s1, 2);
        L0 = L0 * a0 + s0;
        L1 = L1 * a1 + s1;
#pragma unroll
        for (int j = 0; j < 16; j++) {
            accO[j][0] *= a0; accO[j][1] *= a0;
            accO[j][2] *= a1; accO[j][3] *= a1;
        }
        MBAR_WAIT(mbV, (uint32_t)(c & 1));
        // ---- PV ----
#pragma unroll
        for (int p = 0; p < 2; p++) {
#pragma unroll
            for (int kk = 0; kk < 4; kk++) {
                int kt = p * 4 + kk;
                uint32_t kof = kx[kk];
                uint32_t phi[4], plo[4];
                {
                    const float* e0 = accS[2*kt];
                    const float* e1 = accS[2*kt+1];
                    phi[0] = pk2(e0[0], e0[1]);
                    phi[1] = pk2(e0[2], e0[3]);
                    phi[2] = pk2(e1[0], e1[1]);
                    phi[3] = pk2(e1[2], e1[3]);
                    plo[0] = pk2(e0[0] - lo16f(phi[0]), e0[1] - hi16f(phi[0]));
                    plo[1] = pk2(e0[2] - lo16f(phi[1]), e0[3] - hi16f(phi[1]));
                    plo[2] = pk2(e1[0] - lo16f(phi[2]), e1[1] - hi16f(phi[2]));
                    plo[3] = pk2(e1[2] - lo16f(phi[3]), e1[3] - hi16f(phi[3]));
                }
#pragma unroll
                for (int nt = 0; nt < 8; nt++) {
                    uint32_t va = sb + FVB + p * 16384 + (uint32_t)(nt * 16 + lr) * 128u + kof;
                    uint32_t vh_[4], vl_[4];
                    ldsm4(vh_, va); ldsm4(vl_, va + 32768u);
                    mma16816(accO[2*nt],   phi, vh_[0], vh_[2]);
                    mma16816(accO[2*nt],   plo, vh_[0], vh_[2]);
                    mma16816(accO[2*nt],   phi, vl_[0], vl_[2]);
                    mma16816(accO[2*nt+1], phi, vh_[1], vh_[3]);
                    mma16816(accO[2*nt+1], plo, vh_[1], vh_[3]);
                    mma16816(accO[2*nt+1], phi, vl_[1], vl_[3]);
                }
            }
        }
        __syncthreads();
        if (tid == 0 && c + 1 < 8) {
            MBAR_EXPECT(mbV, 65536u);
            BULK_G2S(sb + FVB,          VhP + (size_t)(c + 1) * 32768, 32768u, mbV);
            BULK_G2S(sb + FVB + 32768u, VlP + (size_t)(c + 1) * 32768, 32768u, mbV);
        }
    }

    // epilogue -> att panels [b][kc][nt=qb]
    float i0 = 1.f / L0, i1 = 1.f / L1;
    int r1 = 16 * wid + (lane >> 2);
    int ec = (lane & 3) * 2;
    char* ath = (char*)atth + (size_t)b * NSP * C * 2;
    char* atl = (char*)attl + (size_t)b * NSP * C * 2;
#pragma unroll
    for (int j = 0; j < 16; j++) {
        int cf = j * 8 + ec;
        int kc = h * 2 + (cf >> 6);
        uint32_t cb = ((uint32_t)(cf & 63)) * 2u;
        size_t pb = (size_t)(kc * 8 + qb) * 16384;
        {
            float o0 = accO[j][0] * i0, o1 = accO[j][1] * i0;
            uint32_t ph = pk2(o0, o1);
            uint32_t pl = pk2(o0 - lo16f(ph), o1 - hi16f(ph));
            size_t off = pb + (uint32_t)r1 * 128u + (cb ^ (uint32_t)((r1 & 7) * 16));
            *(uint32_t*)(ath + off) = ph;
            *(uint32_t*)(atl + off) = pl;
        }
        {
            int r2 = r1 + 8;
            float o0 = accO[j][2] * i1, o1 = accO[j][3] * i1;
            uint32_t ph = pk2(o0, o1);
            uint32_t pl = pk2(o0 - lo16f(ph), o1 - hi16f(ph));
            size_t off = pb + (uint32_t)r2 * 128u + (cb ^ (uint32_t)((r2 & 7) * 16));
            *(uint32_t*)(ath + off) = ph;
            *(uint32_t*)(atl + off) = pl;
        }
    }
}

// ---------------- launch ----------------
extern "C" void kernel_launch(void* const* d_in, const int* in_sizes, int n_in,
                              void* d_out, int out_size)
{
    const float* x      = (const float*)d_in[0];
    const float* gamma  = (const float*)d_in[1];
    const float* beta   = (const float*)d_in[2];
    const float* qkv_w  = (const float*)d_in[3];
    const float* qkv_b  = (const float*)d_in[4];
    const float* proj_w = (const float*)d_in[5];
    const float* proj_b = (const float*)d_in[6];
    float* out = (float*)d_out;

    __nv_bfloat16 *xnh, *xnl, *qwh, *qwl, *pwh, *pwl, *Qh, *Ql, *atth, *attl, *Kh, *Kl, *Vh, *Vl;
    cudaGetSymbolAddress((void**)&xnh,  g_xnh);
    cudaGetSymbolAddress((void**)&xnl,  g_xnl);
    cudaGetSymbolAddress((void**)&qwh,  g_qwh);
    cudaGetSymbolAddress((void**)&qwl,  g_qwl);
    cudaGetSymbolAddress((void**)&pwh,  g_pwh);
    cudaGetSymbolAddress((void**)&pwl,  g_pwl);
    cudaGetSymbolAddress((void**)&Qh,   g_Qh);
    cudaGetSymbolAddress((void**)&Ql,   g_Ql);
    cudaGetSymbolAddress((void**)&atth, g_atth);
    cudaGetSymbolAddress((void**)&attl, g_attl);
    cudaGetSymbolAddress((void**)&Kh,   g_Kh);
    cudaGetSymbolAddress((void**)&Kl,   g_Kl);
    cudaGetSymbolAddress((void**)&Vh,   g_Vh);
    cudaGetSymbolAddress((void**)&Vl,   g_Vl);

    const int DSM  = 1024 + 2 * 98304;   // 197632
    const int FDSM = 1024 + 3 * 65536;   // 197632
    cudaFuncSetAttribute(gemm_qkv,     cudaFuncAttributeMaxDynamicSharedMemorySize, DSM);
    cudaFuncSetAttribute(gemm_bf,      cudaFuncAttributeMaxDynamicSharedMemorySize, DSM);
    cudaFuncSetAttribute(flash_kernel, cudaFuncAttributeMaxDynamicSharedMemorySize, FDSM);

    // 0) weight panels
    wcvt_kernel<<<1536, 256>>>(qkv_w, qwh, qwl, 3 * C, 12);
    wcvt_kernel<<<512,  256>>>(proj_w, pwh, pwl, C, 4);

    // 1) GroupNorm -> xn panels
    gn_t_kernel<<<B * NG, 256>>>(x, gamma, beta, xnh, xnl);

    // 2) QKV GEMM -> Q/K/V panels
    gemm_qkv<<<dim3(12, 4, B), 512, DSM>>>(xnh, xnl, qwh, qwl, qkv_b,
                                           Qh, Ql, Kh, Kl, Vh, Vl);

    // 3) fused attention -> att panels
    flash_kernel<<<dim3(8, B * NH), 256, FDSM>>>(Qh, Ql, Kh, Kl, Vh, Vl, atth, attl);

    // 4) proj + bias + residual: out[b][c][n]
    gemm_bf<<<dim3(8, 2, B), 512, DSM>>>(
        pwh, pwl, 4,
        atth, attl, 8, (long long)NSP * C * 2,
        out, NSP, (long long)C * NSP,
        proj_b, x, NSP, (long long)C * NSP);
}

// round 14
// speedup vs baseline: 1.0244x; 1.0244x over previous
#include <cuda_runtime.h>
#include <cuda_bf16.h>
#include <math.h>
#include <stdint.h>

#define B   16
#define C   512
#define NSP 1024
#define NH  4
#define DH  128
#define NG  8
#define SC2 (0.08838834764831845f * 1.4426950408889634f)   // scale * log2(e)

// All GEMM operands stored as pre-swizzled 16KB panels: [128 rows][128 bytes],
// byte-in-row = (col*2) ^ ((row&7)*16).

// ---------------- scratch ----------------
__device__ __nv_bfloat16 g_xnh[(size_t)B*NSP*C];     // [b][kc=8][rt=8] panels
__device__ __nv_bfloat16 g_xnl[(size_t)B*NSP*C];
__device__ __nv_bfloat16 g_qwh[(size_t)3*C*C];       // [kc=8][nt=12] panels
__device__ __nv_bfloat16 g_qwl[(size_t)3*C*C];
__device__ __nv_bfloat16 g_pwh[(size_t)C*C];         // [kc=8][rt=4] panels
__device__ __nv_bfloat16 g_pwl[(size_t)C*C];
__device__ __nv_bfloat16 g_Qh [(size_t)B*NSP*C];     // [b][h][qb=8][kcp=2] panels (scale folded)
__device__ __nv_bfloat16 g_Ql [(size_t)B*NSP*C];
__device__ __nv_bfloat16 g_atth[(size_t)B*NSP*C];    // [b][kc=8][nt=8] panels
__device__ __nv_bfloat16 g_attl[(size_t)B*NSP*C];
__device__ __nv_bfloat16 g_Kh[(size_t)B*NH*NSP*DH];  // [bh][chunk=8][kcp=2] panels
__device__ __nv_bfloat16 g_Kl[(size_t)B*NH*NSP*DH];
__device__ __nv_bfloat16 g_Vh[(size_t)B*NH*NSP*DH];  // [bh][chunk=8][tokp=2] panels (d-rows)
__device__ __nv_bfloat16 g_Vl[(size_t)B*NH*NSP*DH];

// ---------------- helpers ----------------
__device__ __forceinline__ uint32_t smem_u32(const void* p) {
    uint32_t a;
    asm("{ .reg .u64 t; cvta.to.shared.u64 t, %1; cvt.u32.u64 %0, t; }" : "=r"(a) : "l"(p));
    return a;
}
__device__ __forceinline__ void ldsm4(uint32_t* r, uint32_t a) {
    asm volatile("ldmatrix.sync.aligned.m8n8.x4.shared.b16 {%0,%1,%2,%3}, [%4];"
        : "=r"(r[0]), "=r"(r[1]), "=r"(r[2]), "=r"(r[3]) : "r"(a));
}
__device__ __forceinline__ void mma16816(float* d, const uint32_t* a, uint32_t b0, uint32_t b1) {
    asm volatile("mma.sync.aligned.m16n8k16.row.col.f32.bf16.bf16.f32 "
        "{%0,%1,%2,%3}, {%4,%5,%6,%7}, {%8,%9}, {%0,%1,%2,%3};"
        : "+f"(d[0]), "+f"(d[1]), "+f"(d[2]), "+f"(d[3])
        : "r"(a[0]), "r"(a[1]), "r"(a[2]), "r"(a[3]), "r"(b0), "r"(b1));
}
__device__ __forceinline__ uint32_t pk2(float lo, float hi) {
    uint32_t r;
    asm("cvt.rn.bf16x2.f32 %0, %1, %2;" : "=r"(r) : "f"(hi), "f"(lo));
    return r;
}
__device__ __forceinline__ float lo16f(uint32_t u) { return __uint_as_float(u << 16); }
__device__ __forceinline__ float hi16f(uint32_t u) { return __uint_as_float(u & 0xFFFF0000u); }

#define MBAR_INIT(a, cnt) asm volatile("mbarrier.init.shared.b64 [%0], %1;" :: "r"(a), "r"((uint32_t)(cnt)) : "memory")
#define MBAR_EXPECT(a, bytes) asm volatile("mbarrier.arrive.expect_tx.shared.b64 _, [%0], %1;" :: "r"(a), "r"((uint32_t)(bytes)) : "memory")
#define MBAR_WAIT(a, par) do { \
    uint32_t _m = (a); uint32_t _p = (par); uint32_t _d; \
    asm volatile("{\n\t.reg .pred p;\n\tmbarrier.try_wait.parity.acquire.cta.shared::cta.b64 p, [%1], %2;\n\tselp.b32 %0, 1, 0, p;\n\t}" \
        : "=r"(_d) : "r"(_m), "r"(_p) : "memory"); \
    if (!_d) { \
        asm volatile("{\n\t.reg .pred P1;\n\tWL_%=:\n\tmbarrier.try_wait.parity.acquire.cta.shared::cta.b64 P1, [%0], %1, 0x989680;\n\t@P1 bra.uni WD_%=;\n\tbra.uni WL_%=;\n\tWD_%=:\n\t}" \
            :: "r"(_m), "r"(_p) : "memory"); \
    } } while (0)
#define BULK_G2S(dst, src, bytes, mbar) \
    asm volatile("cp.async.bulk.shared::cluster.global.mbarrier::complete_tx::bytes [%0], [%1], %2, [%3];" \
        :: "r"(dst), "l"(src), "r"((uint32_t)(bytes)), "r"(mbar) : "memory")

// ---------------- weight convert -> swizzled panels ----------------
__global__ __launch_bounds__(256) void wcvt_kernel(const float* __restrict__ src,
    __nv_bfloat16* __restrict__ dh, __nv_bfloat16* __restrict__ dl, int O, int tiles)
{
    int i2 = blockIdx.x * 256 + threadIdx.x;
    if (i2 * 2 >= O * C) return;
    int o = (i2 * 2) / C, c = (i2 * 2) % C;
    float v0 = src[(size_t)o * C + c];
    float v1 = src[(size_t)o * C + c + 1];
    __nv_bfloat16 h0 = __float2bfloat16(v0), h1 = __float2bfloat16(v1);
    uint32_t ph = (uint32_t)__bfloat16_as_ushort(h0) | ((uint32_t)__bfloat16_as_ushort(h1) << 16);
    __nv_bfloat16 l0 = __float2bfloat16(v0 - __bfloat162float(h0));
    __nv_bfloat16 l1 = __float2bfloat16(v1 - __bfloat162float(h1));
    uint32_t pl = (uint32_t)__bfloat16_as_ushort(l0) | ((uint32_t)__bfloat16_as_ushort(l1) << 16);
    int panel = (c >> 6) * tiles + (o >> 7);
    int row = o & 127;
    uint32_t off = (uint32_t)panel * 16384u + (uint32_t)row * 128u
                 + ((uint32_t)((c & 63) * 2) ^ (uint32_t)((row & 7) * 16));
    *(uint32_t*)((char*)dh + off) = ph;
    *(uint32_t*)((char*)dl + off) = pl;
}

// ---------------- GroupNorm -> swizzled xn panels [b][kc][rt] ----------------
__global__ __launch_bounds__(256) void gn_t_kernel(
    const float* __restrict__ x, const float* __restrict__ gamma,
    const float* __restrict__ beta,
    __nv_bfloat16* __restrict__ xnh, __nv_bfloat16* __restrict__ xnl)
{
    const int CG = C / NG;
    const int GE = CG * NSP;
    int b = blockIdx.x / NG, g = blockIdx.x % NG;
    const float* xp = x + ((size_t)b * C + (size_t)g * CG) * NSP;
    int t = threadIdx.x;

    float s = 0.f, s2 = 0.f;
    for (int i = t; i < GE; i += 256) { float v = xp[i]; s += v; s2 += v * v; }
    __shared__ float rs[256], rs2[256];
    rs[t] = s; rs2[t] = s2;
    __syncthreads();
    for (int st = 128; st > 0; st >>= 1) {
        if (t < st) { rs[t] += rs[t + st]; rs2[t] += rs2[t + st]; }
        __syncthreads();
    }
    float mu  = rs[0] * (1.f / GE);
    float var = rs2[0] * (1.f / GE) - mu * mu;
    float inv = rsqrtf(var + 1e-5f);

    __shared__ float tile[8][32][33];
    int warp = t >> 5, lane = t & 31;
    for (int tt = warp; tt < 64; tt += 8) {
        int ci = tt >> 5, ni = tt & 31;
        for (int i = 0; i < 32; i++) {
            int c = ci * 32 + i;
            int cg2 = g * CG + c;
            float v = xp[(size_t)c * NSP + ni * 32 + lane];
            tile[warp][i][lane] = (v - mu) * inv * gamma[cg2] + beta[cg2];
        }
        __syncwarp();
        int col = ci * 32 + lane;
        for (int i = 0; i < 32; i++) {
            int n = ni * 32 + i;
            int rt = n >> 7, row = n & 127;
            float v = tile[warp][lane][i];
            __nv_bfloat16 h = __float2bfloat16(v);
            size_t pb = (((size_t)b * 8 + g) * 8 + rt) * 16384;
            uint32_t off = (uint32_t)row * 128u
                         + ((uint32_t)(col * 2) ^ (uint32_t)((row & 7) * 16));
            *(__nv_bfloat16*)((char*)xnh + pb + off) = h;
            *(__nv_bfloat16*)((char*)xnl + pb + off) = __float2bfloat16(v - __bfloat162float(h));
        }
        __syncwarp();
    }
}

// ---------------- GEMM mainloop: 256x128 CTA, 512 thr (16 warps, 32x64 warp tiles) ----------------
#define ST_AL 32768u
#define ST_BH 65536u
#define ST_BL 81920u
#define ST_SZ 98304u

__device__ __forceinline__ void issue_chunk(uint32_t sdst, uint32_t mbar,
    const char* Ah, const char* Al, size_t aoff,
    const char* Bh, const char* Bl, size_t boff)
{
    MBAR_EXPECT(mbar, 98304u);
    BULK_G2S(sdst,         Ah + aoff, 32768u, mbar);
    BULK_G2S(sdst + ST_AL, Al + aoff, 32768u, mbar);
    BULK_G2S(sdst + ST_BH, Bh + boff, 16384u, mbar);
    BULK_G2S(sdst + ST_BL, Bl + boff, 16384u, mbar);
}

__device__ __forceinline__ void gemm_mainloop(uint32_t sbase, uint32_t mb0, uint32_t mb1,
    const char* Ah, const char* Al, int rtA, int RT,
    const char* Bh, const char* Bl, int ntB, int NT,
    int nk, float (&acc)[2][8][4])
{
    const int tid = threadIdx.x, lane = tid & 31, wid = tid >> 5;
    const int warp_m = (wid >> 1) * 32;
    const int warp_n = (wid & 1) * 64;
    const int lr = (lane & 7) + 8 * ((lane >> 3) & 1);
    const int lc = 16 * (lane >> 4);
    const uint32_t rx = (uint32_t)(lr & 7) * 16u;
    uint32_t kx[4];
#pragma unroll
    for (int k = 0; k < 4; k++)
        kx[k] = ((32u * k) ^ (rx & 0x60u)) + ((uint32_t)lc ^ (rx & 0x10u));

    uint32_t rA[2], rB[4];
#pragma unroll
    for (int t = 0; t < 2; t++) {
        int full = warp_m + t * 16 + lr;
        rA[t] = (uint32_t)((full >> 7) * 16384 + (full & 127) * 128);
    }
#pragma unroll
    for (int t = 0; t < 4; t++)
        rB[t] = (uint32_t)(warp_n + t * 16 + lr) * 128u;

    if (tid == 0) {
        issue_chunk(sbase, mb0, Ah, Al, (size_t)(0 * RT + rtA) * 16384,
                    Bh, Bl, (size_t)(0 * NT + ntB) * 16384);
        if (nk > 1)
            issue_chunk(sbase + ST_SZ, mb1, Ah, Al, (size_t)(1 * RT + rtA) * 16384,
                        Bh, Bl, (size_t)(1 * NT + ntB) * 16384);
    }

    for (int i = 0; i < nk; i++) {
        MBAR_WAIT((i & 1) ? mb1 : mb0, (uint32_t)((i >> 1) & 1));

        uint32_t bufA = sbase + (uint32_t)(i & 1) * ST_SZ;
        uint32_t bufB = bufA + ST_BH;
#pragma unroll
        for (int kk = 0; kk < 4; kk++) {
            uint32_t kof = kx[kk];
            uint32_t ah0[4], ah1[4], al0[4], al1[4];
            ldsm4(ah0, bufA + rA[0] + kof);
            ldsm4(ah1, bufA + rA[1] + kof);
            ldsm4(al0, bufA + ST_AL + rA[0] + kof);
            ldsm4(al1, bufA + ST_AL + rA[1] + kof);
#pragma unroll
            for (int nt = 0; nt < 4; nt++) {
                uint32_t bh_[4], bl_[4];
                ldsm4(bh_, bufB + rB[nt] + kof);
                ldsm4(bl_, bufB + 16384u + rB[nt] + kof);
                int j0 = nt * 2, j1 = nt * 2 + 1;
                // term 1: A_hi * B_hi  (4 independent MMAs)
                mma16816(acc[0][j0], ah0, bh_[0], bh_[2]);
                mma16816(acc[1][j0], ah1, bh_[0], bh_[2]);
                mma16816(acc[0][j1], ah0, bh_[1], bh_[3]);
                mma16816(acc[1][j1], ah1, bh_[1], bh_[3]);
                // term 2: A_lo * B_hi  (dependent at distance 4)
                mma16816(acc[0][j0], al0, bh_[0], bh_[2]);
                mma16816(acc[1][j0], al1, bh_[0], bh_[2]);
                mma16816(acc[0][j1], al0, bh_[1], bh_[3]);
                mma16816(acc[1][j1], al1, bh_[1], bh_[3]);
                // term 3: A_hi * B_lo
                mma16816(acc[0][j0], ah0, bl_[0], bl_[2]);
                mma16816(acc[1][j0], ah1, bl_[0], bl_[2]);
                mma16816(acc[0][j1], ah0, bl_[1], bl_[3]);
                mma16816(acc[1][j1], ah1, bl_[1], bl_[3]);
            }
        }
        __syncthreads();
        if (tid == 0 && i + 2 < nk)
            issue_chunk(sbase + (uint32_t)(i & 1) * ST_SZ, (i & 1) ? mb1 : mb0,
                        Ah, Al, (size_t)((i + 2) * RT + rtA) * 16384,
                        Bh, Bl, (size_t)((i + 2) * NT + ntB) * 16384);
    }
}

// ---------------- QKV GEMM with fused Q/K/V panel epilogues ----------------
__global__ __launch_bounds__(512) void gemm_qkv(
    const __nv_bfloat16* __restrict__ xnh, const __nv_bfloat16* __restrict__ xnl,
    const __nv_bfloat16* __restrict__ qwh, const __nv_bfloat16* __restrict__ qwl,
    const float* __restrict__ bias,
    __nv_bfloat16* __restrict__ Qh, __nv_bfloat16* __restrict__ Ql,
    __nv_bfloat16* __restrict__ Kh, __nv_bfloat16* __restrict__ Kl,
    __nv_bfloat16* __restrict__ Vh, __nv_bfloat16* __restrict__ Vl)
{
    extern __shared__ char dsm[];
    char* base = (char*)((((uintptr_t)dsm) + 1023) & ~(uintptr_t)1023);
    const uint32_t sbase = smem_u32(base);
    __shared__ __align__(8) unsigned long long smb[2];
    uint32_t mb0 = smem_u32(&smb[0]), mb1 = smem_u32(&smb[1]);
    const int tid = threadIdx.x, lane = tid & 31, wid = tid >> 5;
    const int bb = blockIdx.z;
    const int nb = blockIdx.x;
    const int m0 = blockIdx.y * 256, n0 = nb * 128;

    if (tid == 0) { MBAR_INIT(mb0, 1); MBAR_INIT(mb1, 1); }
    __syncthreads();

    float acc[2][8][4] = {};
    gemm_mainloop(sbase, mb0, mb1,
        (const char*)xnh + (size_t)bb * NSP * C * 2,
        (const char*)xnl + (size_t)bb * NSP * C * 2, m0 >> 7, 8,
        (const char*)qwh, (const char*)qwl, nb, 12, 8, acc);

    const int warp_m = (wid >> 1) * 32;
    const int warp_n = (wid & 1) * 64;
    const int er = lane >> 2, ec = (lane & 3) * 2;

    if (nb < 4) {
        int h = nb;
#pragma unroll
        for (int mt = 0; mt < 2; mt++)
#pragma unroll
        for (int half = 0; half < 2; half++) {
            int m = m0 + warp_m + mt * 16 + er + half * 8;
            int qb = m >> 7, row = m & 127;
            size_t pb = (((size_t)(bb * NH + h) * 8 + qb) * 2) * 16384;
            uint32_t rowoff = (uint32_t)row * 128u;
            uint32_t rsw = (uint32_t)((row & 7) * 16);
#pragma unroll
            for (int j = 0; j < 8; j++) {
                int n = n0 + warp_n + j * 8 + ec;
                int cl = n & 127;
                float v0 = (acc[mt][j][half * 2 + 0] + bias[n])     * SC2;
                float v1 = (acc[mt][j][half * 2 + 1] + bias[n + 1]) * SC2;
                uint32_t ph = pk2(v0, v1);
                uint32_t pl = pk2(v0 - lo16f(ph), v1 - hi16f(ph));
                size_t off = pb + (size_t)(cl >> 6) * 16384 + rowoff
                           + (((uint32_t)((cl & 63) * 2)) ^ rsw);
                *(uint32_t*)((char*)Qh + off) = ph;
                *(uint32_t*)((char*)Ql + off) = pl;
            }
        }
    } else if (nb < 8) {
        int h = nb - 4;
        size_t pbase = (size_t)(bb * NH + h) * 8 * 32768;
#pragma unroll
        for (int mt = 0; mt < 2; mt++)
#pragma unroll
        for (int half = 0; half < 2; half++) {
            int m = m0 + warp_m + mt * 16 + er + half * 8;
            int mc = m >> 7, row = m & 127;
            size_t cb = pbase + (size_t)mc * 32768;
            uint32_t rowoff = (uint32_t)row * 128u;
            uint32_t rsw = (uint32_t)((row & 7) * 16);
#pragma unroll
            for (int j = 0; j < 8; j++) {
                int dloc = warp_n + j * 8 + ec;
                int n = n0 + dloc;
                float v0 = acc[mt][j][half * 2 + 0] + bias[n];
                float v1 = acc[mt][j][half * 2 + 1] + bias[n + 1];
                uint32_t ph = pk2(v0, v1);
                uint32_t pl = pk2(v0 - lo16f(ph), v1 - hi16f(ph));
                size_t off = cb + (size_t)(dloc >> 6) * 16384 + rowoff
                           + (((uint32_t)((dloc & 63) * 2)) ^ rsw);
                *(uint32_t*)((char*)Kh + off) = ph;
                *(uint32_t*)((char*)Kl + off) = pl;
            }
        }
    } else {
        int h = nb - 8;
        float* vt = (float*)base;
#pragma unroll
        for (int mt = 0; mt < 2; mt++)
#pragma unroll
        for (int half = 0; half < 2; half++) {
            int mloc = warp_m + mt * 16 + er + half * 8;
#pragma unroll
            for (int j = 0; j < 8; j++) {
                int dloc = warp_n + j * 8 + ec;
                int n = n0 + dloc;
                vt[mloc * 129 + dloc]     = acc[mt][j][half * 2 + 0] + bias[n];
                vt[mloc * 129 + dloc + 1] = acc[mt][j][half * 2 + 1] + bias[n + 1];
            }
        }
        __syncthreads();
        size_t pbase = (size_t)(bb * NH + h) * 8 * 32768;
        for (int idx = tid; idx < 16384; idx += 512) {
            int cLoc = idx >> 13;
            int rem = idx & 8191;
            int o2 = rem * 2;
            int p = o2 >> 13, rem2 = o2 & 8191;
            int d = rem2 >> 6, kvc = rem2 & 63;
            int srow = cLoc * 128 + p * 64 + kvc;
            float v0 = vt[srow * 129 + d];
            float v1 = vt[(srow + 1) * 129 + d];
            uint32_t ph = pk2(v0, v1);
            uint32_t pl = pk2(v0 - lo16f(ph), v1 - hi16f(ph));
            size_t off = pbase + (size_t)((m0 >> 7) + cLoc) * 32768
                       + (size_t)p * 16384 + (uint32_t)d * 128u
                       + (((uint32_t)(kvc * 2)) ^ (uint32_t)((d & 7) * 16));
            *(uint32_t*)((char*)Vh + off) = ph;
            *(uint32_t*)((char*)Vl + off) = pl;
        }
    }
}

// ---------------- generic GEMM (proj) ----------------
__global__ __launch_bounds__(512) void gemm_bf(
    const __nv_bfloat16* __restrict__ Ah, const __nv_bfloat16* __restrict__ Al, int RT,
    const __nv_bfloat16* __restrict__ Bh, const __nv_bfloat16* __restrict__ Bl, int NT,
    long long sBb,
    float* __restrict__ Cm, long long ldc, long long sCb,
    const float* __restrict__ bias_m,
    const float* __restrict__ res, long long ldr, long long sRb)
{
    extern __shared__ char dsm[];
    char* base = (char*)((((uintptr_t)dsm) + 1023) & ~(uintptr_t)1023);
    const uint32_t sbase = smem_u32(base);
    __shared__ __align__(8) unsigned long long smb[2];
    uint32_t mb0 = smem_u32(&smb[0]), mb1 = smem_u32(&smb[1]);
    const int tid = threadIdx.x, lane = tid & 31, wid = tid >> 5;
    const int bb = blockIdx.z;
    const int m0 = blockIdx.y * 256, n0 = blockIdx.x * 128;

    if (tid == 0) { MBAR_INIT(mb0, 1); MBAR_INIT(mb1, 1); }
    __syncthreads();

    float acc[2][8][4] = {};
    gemm_mainloop(sbase, mb0, mb1,
        (const char*)Ah, (const char*)Al, m0 >> 7, RT,
        (const char*)Bh + (size_t)bb * sBb, (const char*)Bl + (size_t)bb * sBb,
        n0 >> 7, NT, 8, acc);

    Cm += (size_t)bb * sCb;
    if (res) res += (size_t)bb * sRb;
    const int warp_m = (wid >> 1) * 32, warp_n = (wid & 1) * 64;
    const int er = lane >> 2, ec = (lane & 3) * 2;
#pragma unroll
    for (int mt = 0; mt < 2; mt++)
#pragma unroll
    for (int half = 0; half < 2; half++) {
        int m = m0 + warp_m + mt * 16 + er + half * 8;
        float bm_ = bias_m ? bias_m[m] : 0.f;
#pragma unroll
        for (int j = 0; j < 8; j++) {
            int n = n0 + warp_n + j * 8 + ec;
            float v0 = acc[mt][j][half * 2 + 0] + bm_;
            float v1 = acc[mt][j][half * 2 + 1] + bm_;
            if (res) { const float* rp = res + (size_t)m * ldr + n; v0 += rp[0]; v1 += rp[1]; }
            *(float2*)&Cm[(size_t)m * ldc + n] = make_float2(v0, v1);
        }
    }
}

// ---------------- fused flash attention (R12 layout, term-major MMA order) ----------------
#define FSM_Q 0
#define FSM_K 65536
#define FSM_V 131072

__global__ __launch_bounds__(256) void flash_kernel(
    const __nv_bfloat16* __restrict__ Qh, const __nv_bfloat16* __restrict__ Ql,
    const __nv_bfloat16* __restrict__ Kh, const __nv_bfloat16* __restrict__ Kl,
    const __nv_bfloat16* __restrict__ Vh, const __nv_bfloat16* __restrict__ Vl,
    __nv_bfloat16* __restrict__ atth, __nv_bfloat16* __restrict__ attl)
{
    extern __shared__ char dsm[];
    char* base = (char*)((((uintptr_t)dsm) + 1023) & ~(uintptr_t)1023);
    const uint32_t sb = smem_u32(base);
    __shared__ __align__(8) unsigned long long fmb[2];
    uint32_t mbK = smem_u32(&fmb[0]), mbV = smem_u32(&fmb[1]);
    const int tid = threadIdx.x, lane = tid & 31, wid = tid >> 5;
    const int qb = blockIdx.x;
    const int z = blockIdx.y;
    const int b = z >> 2, h = z & 3;

    const char* KhP = (const char*)Kh + (size_t)z * 8 * 32768;
    const char* KlP = (const char*)Kl + (size_t)z * 8 * 32768;
    const char* VhP = (const char*)Vh + (size_t)z * 8 * 32768;
    const char* VlP = (const char*)Vl + (size_t)z * 8 * 32768;
    const char* QhP = (const char*)Qh + (size_t)((b * NH + h) * 8 + qb) * 32768;
    const char* QlP = (const char*)Ql + (size_t)((b * NH + h) * 8 + qb) * 32768;

    if (tid == 0) { MBAR_INIT(mbK, 1); MBAR_INIT(mbV, 1); }
    __syncthreads();
    if (tid == 0) {
        MBAR_EXPECT(mbK, 131072u);
        BULK_G2S(sb + FSM_Q,          QhP, 32768u, mbK);
        BULK_G2S(sb + FSM_Q + 32768u, QlP, 32768u, mbK);
        BULK_G2S(sb + FSM_K,          KhP, 32768u, mbK);
        BULK_G2S(sb + FSM_K + 32768u, KlP, 32768u, mbK);
        MBAR_EXPECT(mbV, 65536u);
        BULK_G2S(sb + FSM_V,          VhP, 32768u, mbV);
        BULK_G2S(sb + FSM_V + 32768u, VlP, 32768u, mbV);
    }

    const int lr = (lane & 7) + 8 * ((lane >> 3) & 1);
    const int lc = 16 * (lane >> 4);
    const uint32_t rx = (uint32_t)(lr & 7) * 16u;
    uint32_t kx[4];
#pragma unroll
    for (int k = 0; k < 4; k++)
        kx[k] = ((32u * k) ^ (rx & 0x60u)) + ((uint32_t)lc ^ (rx & 0x10u));
    const uint32_t qoff = (uint32_t)(16 * wid + lr) * 128u;

    float accO[16][4] = {};
    float M0 = -1e30f, M1 = -1e30f, L0 = 0.f, L1 = 0.f;

    for (int c = 0; c < 8; c++) {
        float accS[16][4] = {};
        MBAR_WAIT(mbK, (uint32_t)(c & 1));
        // ---- QK: nt-pairs, term-major (dependency distance 4) ----
#pragma unroll
        for (int p = 0; p < 2; p++) {
#pragma unroll
            for (int kk = 0; kk < 4; kk++) {
                uint32_t kof = kx[kk];
                uint32_t qa = sb + FSM_Q + p * 16384 + qoff + kof;
                uint32_t ah[4], al[4];
                ldsm4(ah, qa); ldsm4(al, qa + 32768);
#pragma unroll
                for (int np = 0; np < 4; np++) {
                    int nA = np * 2, nB = np * 2 + 1;
                    uint32_t kaA = sb + FSM_K + p * 16384 + (uint32_t)(nA * 16 + lr) * 128u + kof;
                    uint32_t kaB = sb + FSM_K + p * 16384 + (uint32_t)(nB * 16 + lr) * 128u + kof;
                    uint32_t bAh[4], bAl[4], bBh[4], bBl[4];
                    ldsm4(bAh, kaA); ldsm4(bAl, kaA + 32768);
                    ldsm4(bBh, kaB); ldsm4(bBl, kaB + 32768);
                    // term qh*kh
                    mma16816(accS[2*nA],   ah, bAh[0], bAh[2]);
                    mma16816(accS[2*nA+1], ah, bAh[1], bAh[3]);
                    mma16816(accS[2*nB],   ah, bBh[0], bBh[2]);
                    mma16816(accS[2*nB+1], ah, bBh[1], bBh[3]);
                    // term ql*kh
                    mma16816(accS[2*nA],   al, bAh[0], bAh[2]);
                    mma16816(accS[2*nA+1], al, bAh[1], bAh[3]);
                    mma16816(accS[2*nB],   al, bBh[0], bBh[2]);
                    mma16816(accS[2*nB+1], al, bBh[1], bBh[3]);
                    // term qh*kl
                    mma16816(accS[2*nA],   ah, bAl[0], bAl[2]);
                    mma16816(accS[2*nA+1], ah, bAl[1], bAl[3]);
                    mma16816(accS[2*nB],   ah, bBl[0], bBl[2]);
                    mma16816(accS[2*nB+1], ah, bBl[1], bBl[3]);
                }
            }
        }
        __syncthreads();
        if (tid == 0 && c + 1 < 8) {
            MBAR_EXPECT(mbK, 65536u);
            BULK_G2S(sb + FSM_K,          KhP + (size_t)(c + 1) * 32768, 32768u, mbK);
            BULK_G2S(sb + FSM_K + 32768u, KlP + (size_t)(c + 1) * 32768, 32768u, mbK);
        }
        // ---- online softmax (base-2) ----
        float m0 = -1e30f, m1 = -1e30f;
#pragma unroll
        for (int j = 0; j < 16; j++) {
            m0 = fmaxf(m0, fmaxf(accS[j][0], accS[j][1]));
            m1 = fmaxf(m1, fmaxf(accS[j][2], accS[j][3]));
        }
        m0 = fmaxf(m0, __shfl_xor_sync(0xffffffffu, m0, 1));
        m0 = fmaxf(m0, __shfl_xor_sync(0xffffffffu, m0, 2));
        m1 = fmaxf(m1, __shfl_xor_sync(0xffffffffu, m1, 1));
        m1 = fmaxf(m1, __shfl_xor_sync(0xffffffffu, m1, 2));
        float nM0 = fmaxf(M0, m0), nM1 = fmaxf(M1, m1);
        float a0 = exp2f(M0 - nM0), a1 = exp2f(M1 - nM1);
        M0 = nM0; M1 = nM1;
        float s0 = 0.f, s1 = 0.f;
#pragma unroll
        for (int j = 0; j < 16; j++) {
            accS[j][0] = exp2f(accS[j][0] - M0);
            accS[j][1] = exp2f(accS[j][1] - M0);
            accS[j][2] = exp2f(accS[j][2] - M1);
            accS[j][3] = exp2f(accS[j][3] - M1);
            s0 += accS[j][0] + accS[j][1];
            s1 += accS[j][2] + accS[j][3];
        }
        s0 += __shfl_xor_sync(0xffffffffu, s0, 1);
        s0 += __shfl_xor_sync(0xffffffffu, s0, 2);
        s1 += __shfl_xor_sync(0xffffffffu, s1, 1);
        s1 += __shfl_xor_sync(0xffffffffu, s1, 2);
        L0 = L0 * a0 + s0;
        L1 = L1 * a1 + s1;
#pragma unroll
        for (int j = 0; j < 16; j++) {
            accO[j][0] *= a0; accO[j][1] *= a0;
            accO[j][2] *= a1; accO[j][3] *= a1;
        }
        MBAR_WAIT(mbV, (uint32_t)(c & 1));
        // ---- PV: nt-pairs, term-major ----
#pragma unroll
        for (int p = 0; p < 2; p++) {
#pragma unroll
            for (int kk = 0; kk < 4; kk++) {
                int kt = p * 4 + kk;
                uint32_t kof = kx[kk];
                uint32_t phi[4], plo[4];
                {
                    const float* e0 = accS[2*kt];
                    const float* e1 = accS[2*kt+1];
                    phi[0] = pk2(e0[0], e0[1]);
                    phi[1] = pk2(e0[2], e0[3]);
                    phi[2] = pk2(e1[0], e1[1]);
                    phi[3] = pk2(e1[2], e1[3]);
                    plo[0] = pk2(e0[0] - lo16f(phi[0]), e0[1] - hi16f(phi[0]));
                    plo[1] = pk2(e0[2] - lo16f(phi[1]), e0[3] - hi16f(phi[1]));
                    plo[2] = pk2(e1[0] - lo16f(phi[2]), e1[1] - hi16f(phi[2]));
                    plo[3] = pk2(e1[2] - lo16f(phi[3]), e1[3] - hi16f(phi[3]));
                }
#pragma unroll
                for (int np = 0; np < 4; np++) {
                    int nA = np * 2, nB = np * 2 + 1;
                    uint32_t vaA = sb + FSM_V + p * 16384 + (uint32_t)(nA * 16 + lr) * 128u + kof;
                    uint32_t vaB = sb + FSM_V + p * 16384 + (uint32_t)(nB * 16 + lr) * 128u + kof;
                    uint32_t vAh[4], vAl[4], vBh[4], vBl[4];
                    ldsm4(vAh, vaA); ldsm4(vAl, vaA + 32768);
                    ldsm4(vBh, vaB); ldsm4(vBl, vaB + 32768);
                    // term phi*vh
                    mma16816(accO[2*nA],   phi, vAh[0], vAh[2]);
                    mma16816(accO[2*nA+1], phi, vAh[1], vAh[3]);
                    mma16816(accO[2*nB],   phi, vBh[0], vBh[2]);
                    mma16816(accO[2*nB+1], phi, vBh[1], vBh[3]);
                    // term plo*vh
                    mma16816(accO[2*nA],   plo, vAh[0], vAh[2]);
                    mma16816(accO[2*nA+1], plo, vAh[1], vAh[3]);
                    mma16816(accO[2*nB],   plo, vBh[0], vBh[2]);
                    mma16816(accO[2*nB+1], plo, vBh[1], vBh[3]);
                    // term phi*vl
                    mma16816(accO[2*nA],   phi, vAl[0], vAl[2]);
                    mma16816(accO[2*nA+1], phi, vAl[1], vAl[3]);
                    mma16816(accO[2*nB],   phi, vBl[0], vBl[2]);
                    mma16816(accO[2*nB+1], phi, vBl[1], vBl[3]);
                }
            }
        }
        __syncthreads();
        if (tid == 0 && c + 1 < 8) {
            MBAR_EXPECT(mbV, 65536u);
            BULK_G2S(sb + FSM_V,          VhP + (size_t)(c + 1) * 32768, 32768u, mbV);
            BULK_G2S(sb + FSM_V + 32768u, VlP + (size_t)(c + 1) * 32768, 32768u, mbV);
        }
    }

    // epilogue -> att panels [b][kc][nt=qb]
    float i0 = 1.f / L0, i1 = 1.f / L1;
    int r1 = 16 * wid + (lane >> 2);
    int ec = (lane & 3) * 2;
    char* ath = (char*)atth + (size_t)b * NSP * C * 2;
    char* atl = (char*)attl + (size_t)b * NSP * C * 2;
#pragma unroll
    for (int j = 0; j < 16; j++) {
        int cf = j * 8 + ec;
        int kc = h * 2 + (cf >> 6);
        uint32_t cb = ((uint32_t)(cf & 63)) * 2u;
        size_t pb = (size_t)(kc * 8 + qb) * 16384;
        {
            float o0 = accO[j][0] * i0, o1 = accO[j][1] * i0;
            uint32_t ph = pk2(o0, o1);
            uint32_t pl = pk2(o0 - lo16f(ph), o1 - hi16f(ph));
            size_t off = pb + (uint32_t)r1 * 128u + (cb ^ (uint32_t)((r1 & 7) * 16));
            *(uint32_t*)(ath + off) = ph;
            *(uint32_t*)(atl + off) = pl;
        }
        {
            int r2 = r1 + 8;
            float o0 = accO[j][2] * i1, o1 = accO[j][3] * i1;
            uint32_t ph = pk2(o0, o1);
            uint32_t pl = pk2(o0 - lo16f(ph), o1 - hi16f(ph));
            size_t off = pb + (uint32_t)r2 * 128u + (cb ^ (uint32_t)((r2 & 7) * 16));
            *(uint32_t*)(ath + off) = ph;
            *(uint32_t*)(atl + off) = pl;
        }
    }
}

// ---------------- launch ----------------
extern "C" void kernel_launch(void* const* d_in, const int* in_sizes, int n_in,
                              void* d_out, int out_size)
{
    const float* x      = (const float*)d_in[0];
    const float* gamma  = (const float*)d_in[1];
    const float* beta   = (const float*)d_in[2];
    const float* qkv_w  = (const float*)d_in[3];
    const float* qkv_b  = (const float*)d_in[4];
    const float* proj_w = (const float*)d_in[5];
    const float* proj_b = (const float*)d_in[6];
    float* out = (float*)d_out;

    __nv_bfloat16 *xnh, *xnl, *qwh, *qwl, *pwh, *pwl, *Qh, *Ql, *atth, *attl, *Kh, *Kl, *Vh, *Vl;
    cudaGetSymbolAddress((void**)&xnh,  g_xnh);
    cudaGetSymbolAddress((void**)&xnl,  g_xnl);
    cudaGetSymbolAddress((void**)&qwh,  g_qwh);
    cudaGetSymbolAddress((void**)&qwl,  g_qwl);
    cudaGetSymbolAddress((void**)&pwh,  g_pwh);
    cudaGetSymbolAddress((void**)&pwl,  g_pwl);
    cudaGetSymbolAddress((void**)&Qh,   g_Qh);
    cudaGetSymbolAddress((void**)&Ql,   g_Ql);
    cudaGetSymbolAddress((void**)&atth, g_atth);
    cudaGetSymbolAddress((void**)&attl, g_attl);
    cudaGetSymbolAddress((void**)&Kh,   g_Kh);
    cudaGetSymbolAddress((void**)&Kl,   g_Kl);
    cudaGetSymbolAddress((void**)&Vh,   g_Vh);
    cudaGetSymbolAddress((void**)&Vl,   g_Vl);

    const int DSM  = 1024 + 2 * 98304;   // 197632
    const int FDSM = 1024 + 3 * 65536;   // 197632
    cudaFuncSetAttribute(gemm_qkv,     cudaFuncAttributeMaxDynamicSharedMemorySize, DSM);
    cudaFuncSetAttribute(gemm_bf,      cudaFuncAttributeMaxDynamicSharedMemorySize, DSM);
    cudaFuncSetAttribute(flash_kernel, cudaFuncAttributeMaxDynamicSharedMemorySize, FDSM);

    // 0) weight panels
    wcvt_kernel<<<1536, 256>>>(qkv_w, qwh, qwl, 3 * C, 12);
    wcvt_kernel<<<512,  256>>>(proj_w, pwh, pwl, C, 4);

    // 1) GroupNorm -> xn panels
    gn_t_kernel<<<B * NG, 256>>>(x, gamma, beta, xnh, xnl);

    // 2) QKV GEMM -> Q/K/V panels
    gemm_qkv<<<dim3(12, 4, B), 512, DSM>>>(xnh, xnl, qwh, qwl, qkv_b,
                                           Qh, Ql, Kh, Kl, Vh, Vl);

    // 3) fused attention -> att panels
    flash_kernel<<<dim3(8, B * NH), 256, FDSM>>>(Qh, Ql, Kh, Kl, Vh, Vl, atth, attl);

    // 4) proj + bias + residual: out[b][c][n]
    gemm_bf<<<dim3(8, 2, B), 512, DSM>>>(
        pwh, pwl, 4,
        atth, attl, 8, (long long)NSP * C * 2,
        out, NSP, (long long)C * NSP,
        proj_b, x, NSP, (long long)C * NSP);
}

// round 15
// speedup vs baseline: 1.3930x; 1.3598x over previous
#include <cuda_runtime.h>
#include <cuda_bf16.h>
#include <math.h>
#include <stdint.h>

#define B   16
#define C   512
#define NSP 1024
#define NH  4
#define DH  128
#define NG  8
#define SC2 (0.08838834764831845f * 1.4426950408889634f)   // scale * log2(e)

// All GEMM operands stored as pre-swizzled 16KB panels: [128 rows][128 bytes],
// byte-in-row = (col*2) ^ ((row&7)*16).
// 2-term hi/lo scheme: A-side keeps hi+lo planes, B-side keeps hi only.

// ---------------- scratch ----------------
__device__ __nv_bfloat16 g_xnh[(size_t)B*NSP*C];     // [b][kc=8][rt=8] panels (A-side: hi+lo)
__device__ __nv_bfloat16 g_xnl[(size_t)B*NSP*C];
__device__ __nv_bfloat16 g_qwh[(size_t)3*C*C];       // [kc=8][nt=12] panels (B-side: hi only)
__device__ __nv_bfloat16 g_pwh[(size_t)C*C];         // [kc=8][rt=4] panels (A-side: hi+lo)
__device__ __nv_bfloat16 g_pwl[(size_t)C*C];
__device__ __nv_bfloat16 g_Qh [(size_t)B*NSP*C];     // [b][h][qb=8][kcp=2] panels (A-side hi+lo, scale folded)
__device__ __nv_bfloat16 g_Ql [(size_t)B*NSP*C];
__device__ __nv_bfloat16 g_atth[(size_t)B*NSP*C];    // [b][kc=8][nt=8] panels (B-side: hi only)
__device__ __nv_bfloat16 g_Kh[(size_t)B*NH*NSP*DH];  // [bh][chunk=8][kcp=2] panels (B-side hi)
__device__ __nv_bfloat16 g_Vh[(size_t)B*NH*NSP*DH];  // [bh][chunk=8][tokp=2] panels (B-side hi)

// ---------------- helpers ----------------
__device__ __forceinline__ uint32_t smem_u32(const void* p) {
    uint32_t a;
    asm("{ .reg .u64 t; cvta.to.shared.u64 t, %1; cvt.u32.u64 %0, t; }" : "=r"(a) : "l"(p));
    return a;
}
__device__ __forceinline__ void ldsm4(uint32_t* r, uint32_t a) {
    asm volatile("ldmatrix.sync.aligned.m8n8.x4.shared.b16 {%0,%1,%2,%3}, [%4];"
        : "=r"(r[0]), "=r"(r[1]), "=r"(r[2]), "=r"(r[3]) : "r"(a));
}
__device__ __forceinline__ void mma16816(float* d, const uint32_t* a, uint32_t b0, uint32_t b1) {
    asm volatile("mma.sync.aligned.m16n8k16.row.col.f32.bf16.bf16.f32 "
        "{%0,%1,%2,%3}, {%4,%5,%6,%7}, {%8,%9}, {%0,%1,%2,%3};"
        : "+f"(d[0]), "+f"(d[1]), "+f"(d[2]), "+f"(d[3])
        : "r"(a[0]), "r"(a[1]), "r"(a[2]), "r"(a[3]), "r"(b0), "r"(b1));
}
__device__ __forceinline__ uint32_t pk2(float lo, float hi) {
    uint32_t r;
    asm("cvt.rn.bf16x2.f32 %0, %1, %2;" : "=r"(r) : "f"(hi), "f"(lo));
    return r;
}
__device__ __forceinline__ float lo16f(uint32_t u) { return __uint_as_float(u << 16); }
__device__ __forceinline__ float hi16f(uint32_t u) { return __uint_as_float(u & 0xFFFF0000u); }

#define MBAR_INIT(a, cnt) asm volatile("mbarrier.init.shared.b64 [%0], %1;" :: "r"(a), "r"((uint32_t)(cnt)) : "memory")
#define MBAR_EXPECT(a, bytes) asm volatile("mbarrier.arrive.expect_tx.shared.b64 _, [%0], %1;" :: "r"(a), "r"((uint32_t)(bytes)) : "memory")
#define MBAR_WAIT(a, par) do { \
    uint32_t _m = (a); uint32_t _p = (par); uint32_t _d; \
    asm volatile("{\n\t.reg .pred p;\n\tmbarrier.try_wait.parity.acquire.cta.shared::cta.b64 p, [%1], %2;\n\tselp.b32 %0, 1, 0, p;\n\t}" \
        : "=r"(_d) : "r"(_m), "r"(_p) : "memory"); \
    if (!_d) { \
        asm volatile("{\n\t.reg .pred P1;\n\tWL_%=:\n\tmbarrier.try_wait.parity.acquire.cta.shared::cta.b64 P1, [%0], %1, 0x989680;\n\t@P1 bra.uni WD_%=;\n\tbra.uni WL_%=;\n\tWD_%=:\n\t}" \
            :: "r"(_m), "r"(_p) : "memory"); \
    } } while (0)
#define BULK_G2S(dst, src, bytes, mbar) \
    asm volatile("cp.async.bulk.shared::cluster.global.mbarrier::complete_tx::bytes [%0], [%1], %2, [%3];" \
        :: "r"(dst), "l"(src), "r"((uint32_t)(bytes)), "r"(mbar) : "memory")

// ---------------- weight convert -> swizzled panels ----------------
__global__ __launch_bounds__(256) void wcvt_kernel(const float* __restrict__ src,
    __nv_bfloat16* __restrict__ dh, __nv_bfloat16* __restrict__ dl, int O, int tiles)
{
    int i2 = blockIdx.x * 256 + threadIdx.x;
    if (i2 * 2 >= O * C) return;
    int o = (i2 * 2) / C, c = (i2 * 2) % C;
    float v0 = src[(size_t)o * C + c];
    float v1 = src[(size_t)o * C + c + 1];
    __nv_bfloat16 h0 = __float2bfloat16(v0), h1 = __float2bfloat16(v1);
    uint32_t ph = (uint32_t)__bfloat16_as_ushort(h0) | ((uint32_t)__bfloat16_as_ushort(h1) << 16);
    int panel = (c >> 6) * tiles + (o >> 7);
    int row = o & 127;
    uint32_t off = (uint32_t)panel * 16384u + (uint32_t)row * 128u
                 + ((uint32_t)((c & 63) * 2) ^ (uint32_t)((row & 7) * 16));
    *(uint32_t*)((char*)dh + off) = ph;
    if (dl) {
        __nv_bfloat16 l0 = __float2bfloat16(v0 - __bfloat162float(h0));
        __nv_bfloat16 l1 = __float2bfloat16(v1 - __bfloat162float(h1));
        uint32_t pl = (uint32_t)__bfloat16_as_ushort(l0) | ((uint32_t)__bfloat16_as_ushort(l1) << 16);
        *(uint32_t*)((char*)dl + off) = pl;
    }
}

// ---------------- GroupNorm -> swizzled xn panels [b][kc][rt] ----------------
__global__ __launch_bounds__(256) void gn_t_kernel(
    const float* __restrict__ x, const float* __restrict__ gamma,
    const float* __restrict__ beta,
    __nv_bfloat16* __restrict__ xnh, __nv_bfloat16* __restrict__ xnl)
{
    const int CG = C / NG;
    const int GE = CG * NSP;
    int b = blockIdx.x / NG, g = blockIdx.x % NG;
    const float* xp = x + ((size_t)b * C + (size_t)g * CG) * NSP;
    int t = threadIdx.x;

    float s = 0.f, s2 = 0.f;
    for (int i = t; i < GE; i += 256) { float v = xp[i]; s += v; s2 += v * v; }
    __shared__ float rs[256], rs2[256];
    rs[t] = s; rs2[t] = s2;
    __syncthreads();
    for (int st = 128; st > 0; st >>= 1) {
        if (t < st) { rs[t] += rs[t + st]; rs2[t] += rs2[t + st]; }
        __syncthreads();
    }
    float mu  = rs[0] * (1.f / GE);
    float var = rs2[0] * (1.f / GE) - mu * mu;
    float inv = rsqrtf(var + 1e-5f);

    __shared__ float tile[8][32][33];
    int warp = t >> 5, lane = t & 31;
    for (int tt = warp; tt < 64; tt += 8) {
        int ci = tt >> 5, ni = tt & 31;
        for (int i = 0; i < 32; i++) {
            int c = ci * 32 + i;
            int cg2 = g * CG + c;
            float v = xp[(size_t)c * NSP + ni * 32 + lane];
            tile[warp][i][lane] = (v - mu) * inv * gamma[cg2] + beta[cg2];
        }
        __syncwarp();
        int col = ci * 32 + lane;
        for (int i = 0; i < 32; i++) {
            int n = ni * 32 + i;
            int rt = n >> 7, row = n & 127;
            float v = tile[warp][lane][i];
            __nv_bfloat16 h = __float2bfloat16(v);
            size_t pb = (((size_t)b * 8 + g) * 8 + rt) * 16384;
            uint32_t off = (uint32_t)row * 128u
                         + ((uint32_t)(col * 2) ^ (uint32_t)((row & 7) * 16));
            *(__nv_bfloat16*)((char*)xnh + pb + off) = h;
            *(__nv_bfloat16*)((char*)xnl + pb + off) = __float2bfloat16(v - __bfloat162float(h));
        }
        __syncwarp();
    }
}

// ---------------- GEMM mainloop: 256x128 CTA, 512 thr, 2-term ----------------
#define GST_AL 32768u
#define GST_BH 65536u
#define GST_SZ 81920u

__device__ __forceinline__ void issue_chunk(uint32_t sdst, uint32_t mbar,
    const char* Ah, const char* Al, size_t aoff,
    const char* Bh, size_t boff)
{
    MBAR_EXPECT(mbar, 81920u);
    BULK_G2S(sdst,          Ah + aoff, 32768u, mbar);
    BULK_G2S(sdst + GST_AL, Al + aoff, 32768u, mbar);
    BULK_G2S(sdst + GST_BH, Bh + boff, 16384u, mbar);
}

__device__ __forceinline__ void gemm_mainloop(uint32_t sbase, uint32_t mb0, uint32_t mb1,
    const char* Ah, const char* Al, int rtA, int RT,
    const char* Bh, int ntB, int NT,
    int nk, float (&acc)[2][8][4])
{
    const int tid = threadIdx.x, lane = tid & 31, wid = tid >> 5;
    const int warp_m = (wid >> 1) * 32;
    const int warp_n = (wid & 1) * 64;
    const int lr = (lane & 7) + 8 * ((lane >> 3) & 1);
    const int lc = 16 * (lane >> 4);
    const uint32_t rx = (uint32_t)(lr & 7) * 16u;
    uint32_t kx[4];
#pragma unroll
    for (int k = 0; k < 4; k++)
        kx[k] = ((32u * k) ^ (rx & 0x60u)) + ((uint32_t)lc ^ (rx & 0x10u));

    uint32_t rA[2], rB[4];
#pragma unroll
    for (int t = 0; t < 2; t++) {
        int full = warp_m + t * 16 + lr;
        rA[t] = (uint32_t)((full >> 7) * 16384 + (full & 127) * 128);
    }
#pragma unroll
    for (int t = 0; t < 4; t++)
        rB[t] = (uint32_t)(warp_n + t * 16 + lr) * 128u;

    if (tid == 0) {
        issue_chunk(sbase, mb0, Ah, Al, (size_t)(0 * RT + rtA) * 16384,
                    Bh, (size_t)(0 * NT + ntB) * 16384);
        if (nk > 1)
            issue_chunk(sbase + GST_SZ, mb1, Ah, Al, (size_t)(1 * RT + rtA) * 16384,
                        Bh, (size_t)(1 * NT + ntB) * 16384);
    }

    for (int i = 0; i < nk; i++) {
        MBAR_WAIT((i & 1) ? mb1 : mb0, (uint32_t)((i >> 1) & 1));

        uint32_t bufA = sbase + (uint32_t)(i & 1) * GST_SZ;
        uint32_t bufB = bufA + GST_BH;
#pragma unroll
        for (int kk = 0; kk < 4; kk++) {
            uint32_t kof = kx[kk];
            uint32_t ah0[4], ah1[4], al0[4], al1[4];
            ldsm4(ah0, bufA + rA[0] + kof);
            ldsm4(ah1, bufA + rA[1] + kof);
            ldsm4(al0, bufA + GST_AL + rA[0] + kof);
            ldsm4(al1, bufA + GST_AL + rA[1] + kof);
#pragma unroll
            for (int nt = 0; nt < 4; nt++) {
                uint32_t bh_[4];
                ldsm4(bh_, bufB + rB[nt] + kof);
                int j0 = nt * 2, j1 = nt * 2 + 1;
                mma16816(acc[0][j0], ah0, bh_[0], bh_[2]);
                mma16816(acc[1][j0], ah1, bh_[0], bh_[2]);
                mma16816(acc[0][j1], ah0, bh_[1], bh_[3]);
                mma16816(acc[1][j1], ah1, bh_[1], bh_[3]);
                mma16816(acc[0][j0], al0, bh_[0], bh_[2]);
                mma16816(acc[1][j0], al1, bh_[0], bh_[2]);
                mma16816(acc[0][j1], al0, bh_[1], bh_[3]);
                mma16816(acc[1][j1], al1, bh_[1], bh_[3]);
            }
        }
        __syncthreads();
        if (tid == 0 && i + 2 < nk)
            issue_chunk(sbase + (uint32_t)(i & 1) * GST_SZ, (i & 1) ? mb1 : mb0,
                        Ah, Al, (size_t)((i + 2) * RT + rtA) * 16384,
                        Bh, (size_t)((i + 2) * NT + ntB) * 16384);
    }
}

// ---------------- QKV GEMM with fused Q/K/V panel epilogues ----------------
__global__ __launch_bounds__(512) void gemm_qkv(
    const __nv_bfloat16* __restrict__ xnh, const __nv_bfloat16* __restrict__ xnl,
    const __nv_bfloat16* __restrict__ qwh,
    const float* __restrict__ bias,
    __nv_bfloat16* __restrict__ Qh, __nv_bfloat16* __restrict__ Ql,
    __nv_bfloat16* __restrict__ Kh, __nv_bfloat16* __restrict__ Vh)
{
    extern __shared__ char dsm[];
    char* base = (char*)((((uintptr_t)dsm) + 1023) & ~(uintptr_t)1023);
    const uint32_t sbase = smem_u32(base);
    __shared__ __align__(8) unsigned long long smb[2];
    uint32_t mb0 = smem_u32(&smb[0]), mb1 = smem_u32(&smb[1]);
    const int tid = threadIdx.x, lane = tid & 31, wid = tid >> 5;
    const int bb = blockIdx.z;
    const int nb = blockIdx.x;
    const int m0 = blockIdx.y * 256, n0 = nb * 128;

    if (tid == 0) { MBAR_INIT(mb0, 1); MBAR_INIT(mb1, 1); }
    __syncthreads();

    float acc[2][8][4] = {};
    gemm_mainloop(sbase, mb0, mb1,
        (const char*)xnh + (size_t)bb * NSP * C * 2,
        (const char*)xnl + (size_t)bb * NSP * C * 2, m0 >> 7, 8,
        (const char*)qwh, nb, 12, 8, acc);

    const int warp_m = (wid >> 1) * 32;
    const int warp_n = (wid & 1) * 64;
    const int er = lane >> 2, ec = (lane & 3) * 2;

    if (nb < 4) {
        int h = nb;
#pragma unroll
        for (int mt = 0; mt < 2; mt++)
#pragma unroll
        for (int half = 0; half < 2; half++) {
            int m = m0 + warp_m + mt * 16 + er + half * 8;
            int qb = m >> 7, row = m & 127;
            size_t pb = (((size_t)(bb * NH + h) * 8 + qb) * 2) * 16384;
            uint32_t rowoff = (uint32_t)row * 128u;
            uint32_t rsw = (uint32_t)((row & 7) * 16);
#pragma unroll
            for (int j = 0; j < 8; j++) {
                int n = n0 + warp_n + j * 8 + ec;
                int cl = n & 127;
                float v0 = (acc[mt][j][half * 2 + 0] + bias[n])     * SC2;
                float v1 = (acc[mt][j][half * 2 + 1] + bias[n + 1]) * SC2;
                uint32_t ph = pk2(v0, v1);
                uint32_t pl = pk2(v0 - lo16f(ph), v1 - hi16f(ph));
                size_t off = pb + (size_t)(cl >> 6) * 16384 + rowoff
                           + (((uint32_t)((cl & 63) * 2)) ^ rsw);
                *(uint32_t*)((char*)Qh + off) = ph;
                *(uint32_t*)((char*)Ql + off) = pl;
            }
        }
    } else if (nb < 8) {
        int h = nb - 4;
        size_t pbase = (size_t)(bb * NH + h) * 8 * 32768;
#pragma unroll
        for (int mt = 0; mt < 2; mt++)
#pragma unroll
        for (int half = 0; half < 2; half++) {
            int m = m0 + warp_m + mt * 16 + er + half * 8;
            int mc = m >> 7, row = m & 127;
            size_t cb = pbase + (size_t)mc * 32768;
            uint32_t rowoff = (uint32_t)row * 128u;
            uint32_t rsw = (uint32_t)((row & 7) * 16);
#pragma unroll
            for (int j = 0; j < 8; j++) {
                int dloc = warp_n + j * 8 + ec;
                int n = n0 + dloc;
                float v0 = acc[mt][j][half * 2 + 0] + bias[n];
                float v1 = acc[mt][j][half * 2 + 1] + bias[n + 1];
                uint32_t ph = pk2(v0, v1);
                size_t off = cb + (size_t)(dloc >> 6) * 16384 + rowoff
                           + (((uint32_t)((dloc & 63) * 2)) ^ rsw);
                *(uint32_t*)((char*)Kh + off) = ph;
            }
        }
    } else {
        int h = nb - 8;
        float* vt = (float*)base;
#pragma unroll
        for (int mt = 0; mt < 2; mt++)
#pragma unroll
        for (int half = 0; half < 2; half++) {
            int mloc = warp_m + mt * 16 + er + half * 8;
#pragma unroll
            for (int j = 0; j < 8; j++) {
                int dloc = warp_n + j * 8 + ec;
                int n = n0 + dloc;
                vt[mloc * 129 + dloc]     = acc[mt][j][half * 2 + 0] + bias[n];
                vt[mloc * 129 + dloc + 1] = acc[mt][j][half * 2 + 1] + bias[n + 1];
            }
        }
        __syncthreads();
        size_t pbase = (size_t)(bb * NH + h) * 8 * 32768;
        for (int idx = tid; idx < 16384; idx += 512) {
            int cLoc = idx >> 13;
            int rem = idx & 8191;
            int o2 = rem * 2;
            int p = o2 >> 13, rem2 = o2 & 8191;
            int d = rem2 >> 6, kvc = rem2 & 63;
            int srow = cLoc * 128 + p * 64 + kvc;
            float v0 = vt[srow * 129 + d];
            float v1 = vt[(srow + 1) * 129 + d];
            uint32_t ph = pk2(v0, v1);
            size_t off = pbase + (size_t)((m0 >> 7) + cLoc) * 32768
                       + (size_t)p * 16384 + (uint32_t)d * 128u
                       + (((uint32_t)(kvc * 2)) ^ (uint32_t)((d & 7) * 16));
            *(uint32_t*)((char*)Vh + off) = ph;
        }
    }
}

// ---------------- generic GEMM (proj): A = pw hi/lo, B = atth ----------------
__global__ __launch_bounds__(512) void gemm_bf(
    const __nv_bfloat16* __restrict__ Ah, const __nv_bfloat16* __restrict__ Al, int RT,
    const __nv_bfloat16* __restrict__ Bh, int NT, long long sBb,
    float* __restrict__ Cm, long long ldc, long long sCb,
    const float* __restrict__ bias_m,
    const float* __restrict__ res, long long ldr, long long sRb)
{
    extern __shared__ char dsm[];
    char* base = (char*)((((uintptr_t)dsm) + 1023) & ~(uintptr_t)1023);
    const uint32_t sbase = smem_u32(base);
    __shared__ __align__(8) unsigned long long smb[2];
    uint32_t mb0 = smem_u32(&smb[0]), mb1 = smem_u32(&smb[1]);
    const int tid = threadIdx.x, lane = tid & 31, wid = tid >> 5;
    const int bb = blockIdx.z;
    const int m0 = blockIdx.y * 256, n0 = blockIdx.x * 128;

    if (tid == 0) { MBAR_INIT(mb0, 1); MBAR_INIT(mb1, 1); }
    __syncthreads();

    float acc[2][8][4] = {};
    gemm_mainloop(sbase, mb0, mb1,
        (const char*)Ah, (const char*)Al, m0 >> 7, RT,
        (const char*)Bh + (size_t)bb * sBb, n0 >> 7, NT, 8, acc);

    Cm += (size_t)bb * sCb;
    if (res) res += (size_t)bb * sRb;
    const int warp_m = (wid >> 1) * 32, warp_n = (wid & 1) * 64;
    const int er = lane >> 2, ec = (lane & 3) * 2;
#pragma unroll
    for (int mt = 0; mt < 2; mt++)
#pragma unroll
    for (int half = 0; half < 2; half++) {
        int m = m0 + warp_m + mt * 16 + er + half * 8;
        float bm_ = bias_m ? bias_m[m] : 0.f;
#pragma unroll
        for (int j = 0; j < 8; j++) {
            int n = n0 + warp_n + j * 8 + ec;
            float v0 = acc[mt][j][half * 2 + 0] + bm_;
            float v1 = acc[mt][j][half * 2 + 1] + bm_;
            if (res) { const float* rp = res + (size_t)m * ldr + n; v0 += rp[0]; v1 += rp[1]; }
            *(float2*)&Cm[(size_t)m * ldc + n] = make_float2(v0, v1);
        }
    }
}

// ---------------- flash attention: Q smem hi/lo, K+V hi double-buffered ----------------
#define FQB  0u
#define FKB  65536u
#define FVB  131072u

__global__ __launch_bounds__(256) void flash_kernel(
    const __nv_bfloat16* __restrict__ Qh, const __nv_bfloat16* __restrict__ Ql,
    const __nv_bfloat16* __restrict__ Kh, const __nv_bfloat16* __restrict__ Vh,
    __nv_bfloat16* __restrict__ atth)
{
    extern __shared__ char dsm[];
    char* base = (char*)((((uintptr_t)dsm) + 1023) & ~(uintptr_t)1023);
    const uint32_t sb = smem_u32(base);
    __shared__ __align__(8) unsigned long long fmb[5];
    uint32_t mbQ  = smem_u32(&fmb[0]);
    uint32_t mbK0 = smem_u32(&fmb[1]), mbK1 = smem_u32(&fmb[2]);
    uint32_t mbV0 = smem_u32(&fmb[3]), mbV1 = smem_u32(&fmb[4]);
    const int tid = threadIdx.x, lane = tid & 31, wid = tid >> 5;
    const int qb = blockIdx.x;
    const int z = blockIdx.y;
    const int b = z >> 2, h = z & 3;

    const char* KhP = (const char*)Kh + (size_t)z * 8 * 32768;
    const char* VhP = (const char*)Vh + (size_t)z * 8 * 32768;
    const char* QhP = (const char*)Qh + (size_t)((b * NH + h) * 8 + qb) * 32768;
    const char* QlP = (const char*)Ql + (size_t)((b * NH + h) * 8 + qb) * 32768;

    if (tid == 0) {
        MBAR_INIT(mbQ, 1); MBAR_INIT(mbK0, 1); MBAR_INIT(mbK1, 1);
        MBAR_INIT(mbV0, 1); MBAR_INIT(mbV1, 1);
    }
    __syncthreads();
    if (tid == 0) {
        MBAR_EXPECT(mbQ, 65536u);
        BULK_G2S(sb + FQB,          QhP, 32768u, mbQ);
        BULK_G2S(sb + FQB + 32768u, QlP, 32768u, mbQ);
        MBAR_EXPECT(mbK0, 32768u);
        BULK_G2S(sb + FKB,          KhP, 32768u, mbK0);
        MBAR_EXPECT(mbK1, 32768u);
        BULK_G2S(sb + FKB + 32768u, KhP + 32768, 32768u, mbK1);
        MBAR_EXPECT(mbV0, 32768u);
        BULK_G2S(sb + FVB,          VhP, 32768u, mbV0);
        MBAR_EXPECT(mbV1, 32768u);
        BULK_G2S(sb + FVB + 32768u, VhP + 32768, 32768u, mbV1);
    }

    const int lr = (lane & 7) + 8 * ((lane >> 3) & 1);
    const int lc = 16 * (lane >> 4);
    const uint32_t rx = (uint32_t)(lr & 7) * 16u;
    uint32_t kx[4];
#pragma unroll
    for (int k = 0; k < 4; k++)
        kx[k] = ((32u * k) ^ (rx & 0x60u)) + ((uint32_t)lc ^ (rx & 0x10u));
    const uint32_t qoff = (uint32_t)(16 * wid + lr) * 128u;

    MBAR_WAIT(mbQ, 0u);

    float accO[16][4] = {};
    float M0 = -1e30f, M1 = -1e30f, L0 = 0.f, L1 = 0.f;

    for (int c = 0; c < 8; c++) {
        float accS[16][4] = {};
        uint32_t kb = sb + FKB + (uint32_t)(c & 1) * 32768u;
        MBAR_WAIT((c & 1) ? mbK1 : mbK0, (uint32_t)((c >> 1) & 1));
        // ---- QK: Q(hi,lo) x K(hi) ----
#pragma unroll
        for (int p = 0; p < 2; p++) {
#pragma unroll
            for (int kk = 0; kk < 4; kk++) {
                uint32_t kof = kx[kk];
                uint32_t qa = sb + FQB + p * 16384 + qoff + kof;
                uint32_t ah[4], al[4];
                ldsm4(ah, qa); ldsm4(al, qa + 32768u);
#pragma unroll
                for (int nt = 0; nt < 8; nt++) {
                    uint32_t ka = kb + p * 16384 + (uint32_t)(nt * 16 + lr) * 128u + kof;
                    uint32_t bh_[4];
                    ldsm4(bh_, ka);
                    mma16816(accS[2*nt],   ah, bh_[0], bh_[2]);
                    mma16816(accS[2*nt+1], ah, bh_[1], bh_[3]);
                    mma16816(accS[2*nt],   al, bh_[0], bh_[2]);
                    mma16816(accS[2*nt+1], al, bh_[1], bh_[3]);
                }
            }
        }
        __syncthreads();
        if (tid == 0 && c + 2 < 8) {
            uint32_t mk = (c & 1) ? mbK1 : mbK0;
            MBAR_EXPECT(mk, 32768u);
            BULK_G2S(kb, KhP + (size_t)(c + 2) * 32768, 32768u, mk);
        }
        // ---- online softmax (base-2) ----
        float m0 = -1e30f, m1 = -1e30f;
#pragma unroll
        for (int j = 0; j < 16; j++) {
            m0 = fmaxf(m0, fmaxf(accS[j][0], accS[j][1]));
            m1 = fmaxf(m1, fmaxf(accS[j][2], accS[j][3]));
        }
        m0 = fmaxf(m0, __shfl_xor_sync(0xffffffffu, m0, 1));
        m0 = fmaxf(m0, __shfl_xor_sync(0xffffffffu, m0, 2));
        m1 = fmaxf(m1, __shfl_xor_sync(0xffffffffu, m1, 1));
        m1 = fmaxf(m1, __shfl_xor_sync(0xffffffffu, m1, 2));
        float nM0 = fmaxf(M0, m0), nM1 = fmaxf(M1, m1);
        float a0 = exp2f(M0 - nM0), a1 = exp2f(M1 - nM1);
        M0 = nM0; M1 = nM1;
        float s0 = 0.f, s1 = 0.f;
#pragma unroll
        for (int j = 0; j < 16; j++) {
            accS[j][0] = exp2f(accS[j][0] - M0);
            accS[j][1] = exp2f(accS[j][1] - M0);
            accS[j][2] = exp2f(accS[j][2] - M1);
            accS[j][3] = exp2f(accS[j][3] - M1);
            s0 += accS[j][0] + accS[j][1];
            s1 += accS[j][2] + accS[j][3];
        }
        s0 += __shfl_xor_sync(0xffffffffu, s0, 1);
        s0 += __shfl_xor_sync(0xffffffffu, s0, 2);
        s1 += __shfl_xor_sync(0xffffffffu, s1, 1);
        s1 += __shfl_xor_sync(0xffffffffu, s1, 2);
        L0 = L0 * a0 + s0;
        L1 = L1 * a1 + s1;
#pragma unroll
        for (int j = 0; j < 16; j++) {
            accO[j][0] *= a0; accO[j][1] *= a0;
            accO[j][2] *= a1; accO[j][3] *= a1;
        }
        uint32_t vb = sb + FVB + (uint32_t)(c & 1) * 32768u;
        MBAR_WAIT((c & 1) ? mbV1 : mbV0, (uint32_t)((c >> 1) & 1));
        // ---- PV: P(hi,lo) x V(hi) ----
#pragma unroll
        for (int p = 0; p < 2; p++) {
#pragma unroll
            for (int kk = 0; kk < 4; kk++) {
                int kt = p * 4 + kk;
                uint32_t kof = kx[kk];
                uint32_t phi[4], plo[4];
                {
                    const float* e0 = accS[2*kt];
                    const float* e1 = accS[2*kt+1];
                    phi[0] = pk2(e0[0], e0[1]);
                    phi[1] = pk2(e0[2], e0[3]);
                    phi[2] = pk2(e1[0], e1[1]);
                    phi[3] = pk2(e1[2], e1[3]);
                    plo[0] = pk2(e0[0] - lo16f(phi[0]), e0[1] - hi16f(phi[0]));
                    plo[1] = pk2(e0[2] - lo16f(phi[1]), e0[3] - hi16f(phi[1]));
                    plo[2] = pk2(e1[0] - lo16f(phi[2]), e1[1] - hi16f(phi[2]));
                    plo[3] = pk2(e1[2] - lo16f(phi[3]), e1[3] - hi16f(phi[3]));
                }
#pragma unroll
                for (int nt = 0; nt < 8; nt++) {
                    uint32_t va = vb + p * 16384 + (uint32_t)(nt * 16 + lr) * 128u + kof;
                    uint32_t vh_[4];
                    ldsm4(vh_, va);
                    mma16816(accO[2*nt],   phi, vh_[0], vh_[2]);
                    mma16816(accO[2*nt+1], phi, vh_[1], vh_[3]);
                    mma16816(accO[2*nt],   plo, vh_[0], vh_[2]);
                    mma16816(accO[2*nt+1], plo, vh_[1], vh_[3]);
                }
            }
        }
        __syncthreads();
        if (tid == 0 && c + 2 < 8) {
            uint32_t mv = (c & 1) ? mbV1 : mbV0;
            MBAR_EXPECT(mv, 32768u);
            BULK_G2S(vb, VhP + (size_t)(c + 2) * 32768, 32768u, mv);
        }
    }

    // epilogue -> att panels [b][kc][nt=qb], hi only
    float i0 = 1.f / L0, i1 = 1.f / L1;
    int r1 = 16 * wid + (lane >> 2);
    int ec = (lane & 3) * 2;
    char* ath = (char*)atth + (size_t)b * NSP * C * 2;
#pragma unroll
    for (int j = 0; j < 16; j++) {
        int cf = j * 8 + ec;
        int kc = h * 2 + (cf >> 6);
        uint32_t cb = ((uint32_t)(cf & 63)) * 2u;
        size_t pb = (size_t)(kc * 8 + qb) * 16384;
        {
            float o0 = accO[j][0] * i0, o1 = accO[j][1] * i0;
            size_t off = pb + (uint32_t)r1 * 128u + (cb ^ (uint32_t)((r1 & 7) * 16));
            *(uint32_t*)(ath + off) = pk2(o0, o1);
        }
        {
            int r2 = r1 + 8;
            float o0 = accO[j][2] * i1, o1 = accO[j][3] * i1;
            size_t off = pb + (uint32_t)r2 * 128u + (cb ^ (uint32_t)((r2 & 7) * 16));
            *(uint32_t*)(ath + off) = pk2(o0, o1);
        }
    }
}

// ---------------- launch ----------------
extern "C" void kernel_launch(void* const* d_in, const int* in_sizes, int n_in,
                              void* d_out, int out_size)
{
    const float* x      = (const float*)d_in[0];
    const float* gamma  = (const float*)d_in[1];
    const float* beta   = (const float*)d_in[2];
    const float* qkv_w  = (const float*)d_in[3];
    const float* qkv_b  = (const float*)d_in[4];
    const float* proj_w = (const float*)d_in[5];
    const float* proj_b = (const float*)d_in[6];
    float* out = (float*)d_out;

    __nv_bfloat16 *xnh, *xnl, *qwh, *pwh, *pwl, *Qh, *Ql, *atth, *Kh, *Vh;
    cudaGetSymbolAddress((void**)&xnh,  g_xnh);
    cudaGetSymbolAddress((void**)&xnl,  g_xnl);
    cudaGetSymbolAddress((void**)&qwh,  g_qwh);
    cudaGetSymbolAddress((void**)&pwh,  g_pwh);
    cudaGetSymbolAddress((void**)&pwl,  g_pwl);
    cudaGetSymbolAddress((void**)&Qh,   g_Qh);
    cudaGetSymbolAddress((void**)&Ql,   g_Ql);
    cudaGetSymbolAddress((void**)&atth, g_atth);
    cudaGetSymbolAddress((void**)&Kh,   g_Kh);
    cudaGetSymbolAddress((void**)&Vh,   g_Vh);

    const int DSM  = 1024 + 2 * 81920;   // 164864
    const int FDSM = 1024 + 196608;      // 197632
    cudaFuncSetAttribute(gemm_qkv,     cudaFuncAttributeMaxDynamicSharedMemorySize, DSM);
    cudaFuncSetAttribute(gemm_bf,      cudaFuncAttributeMaxDynamicSharedMemorySize, DSM);
    cudaFuncSetAttribute(flash_kernel, cudaFuncAttributeMaxDynamicSharedMemorySize, FDSM);

    // 0) weight panels (qkv: B-side hi only; proj: A-side hi+lo)
    wcvt_kernel<<<1536, 256>>>(qkv_w, qwh, (__nv_bfloat16*)nullptr, 3 * C, 12);
    wcvt_kernel<<<512,  256>>>(proj_w, pwh, pwl, C, 4);

    // 1) GroupNorm -> xn panels (hi+lo)
    gn_t_kernel<<<B * NG, 256>>>(x, gamma, beta, xnh, xnl);

    // 2) QKV GEMM -> Q(hi/lo), K(hi), V(hi)
    gemm_qkv<<<dim3(12, 4, B), 512, DSM>>>(xnh, xnl, qwh, qkv_b, Qh, Ql, Kh, Vh);

    // 3) fused attention -> att panels (hi)
    flash_kernel<<<dim3(8, B * NH), 256, FDSM>>>(Qh, Ql, Kh, Vh, atth);

    // 4) proj + bias + residual: out[b][c][n]
    gemm_bf<<<dim3(8, 2, B), 512, DSM>>>(
        pwh, pwl, 4,
        atth, 8, (long long)NSP * C * 2,
        out, NSP, (long long)C * NSP,
        proj_b, x, NSP, (long long)C * NSP);
}

// round 17
// speedup vs baseline: 2.2529x; 1.6173x over previous
#include <cuda_runtime.h>
#include <cuda_bf16.h>
#include <math.h>
#include <stdint.h>

#define B   16
#define C   512
#define NSP 1024
#define NH  4
#define DH  128
#define NG  8
#define SC2 (0.08838834764831845f * 1.4426950408889634f)   // scale * log2(e)

// All GEMM operands stored as pre-swizzled 16KB panels: [128 rows][128 bytes],
// byte-in-row = (col*2) ^ ((row&7)*16).  Pure bf16 single-term scheme.

// ---------------- scratch ----------------
__device__ __nv_bfloat16 g_xnh[(size_t)B*NSP*C];     // [b][kc=8][rt=8] panels
__device__ __nv_bfloat16 g_qwh[(size_t)3*C*C];       // [kc=8][nt=12] panels
__device__ __nv_bfloat16 g_pwh[(size_t)C*C];         // [kc=8][rt=4] panels
__device__ __nv_bfloat16 g_Qh [(size_t)B*NSP*C];     // [b][h][qb=8][kcp=2] panels (scale folded)
__device__ __nv_bfloat16 g_atth[(size_t)B*NSP*C];    // [b][kc=8][nt=8] panels
__device__ __nv_bfloat16 g_Kh[(size_t)B*NH*NSP*DH];  // [bh][chunk=8][kcp=2] panels
__device__ __nv_bfloat16 g_Vh[(size_t)B*NH*NSP*DH];  // [bh][chunk=8][tokp=2] panels (d-rows)

// ---------------- helpers ----------------
__device__ __forceinline__ uint32_t smem_u32(const void* p) {
    uint32_t a;
    asm("{ .reg .u64 t; cvta.to.shared.u64 t, %1; cvt.u32.u64 %0, t; }" : "=r"(a) : "l"(p));
    return a;
}
__device__ __forceinline__ void ldsm4(uint32_t* r, uint32_t a) {
    asm volatile("ldmatrix.sync.aligned.m8n8.x4.shared.b16 {%0,%1,%2,%3}, [%4];"
        : "=r"(r[0]), "=r"(r[1]), "=r"(r[2]), "=r"(r[3]) : "r"(a));
}
__device__ __forceinline__ void mma16816(float* d, const uint32_t* a, uint32_t b0, uint32_t b1) {
    asm volatile("mma.sync.aligned.m16n8k16.row.col.f32.bf16.bf16.f32 "
        "{%0,%1,%2,%3}, {%4,%5,%6,%7}, {%8,%9}, {%0,%1,%2,%3};"
        : "+f"(d[0]), "+f"(d[1]), "+f"(d[2]), "+f"(d[3])
        : "r"(a[0]), "r"(a[1]), "r"(a[2]), "r"(a[3]), "r"(b0), "r"(b1));
}
__device__ __forceinline__ uint32_t pk2(float lo, float hi) {
    uint32_t r;
    asm("cvt.rn.bf16x2.f32 %0, %1, %2;" : "=r"(r) : "f"(hi), "f"(lo));
    return r;
}

#define MBAR_INIT(a, cnt) asm volatile("mbarrier.init.shared.b64 [%0], %1;" :: "r"(a), "r"((uint32_t)(cnt)) : "memory")
#define MBAR_EXPECT(a, bytes) asm volatile("mbarrier.arrive.expect_tx.shared.b64 _, [%0], %1;" :: "r"(a), "r"((uint32_t)(bytes)) : "memory")
#define MBAR_WAIT(a, par) do { \
    uint32_t _m = (a); uint32_t _p = (par); uint32_t _d; \
    asm volatile("{\n\t.reg .pred p;\n\tmbarrier.try_wait.parity.acquire.cta.shared::cta.b64 p, [%1], %2;\n\tselp.b32 %0, 1, 0, p;\n\t}" \
        : "=r"(_d) : "r"(_m), "r"(_p) : "memory"); \
    if (!_d) { \
        asm volatile("{\n\t.reg .pred P1;\n\tWL_%=:\n\tmbarrier.try_wait.parity.acquire.cta.shared::cta.b64 P1, [%0], %1, 0x989680;\n\t@P1 bra.uni WD_%=;\n\tbra.uni WL_%=;\n\tWD_%=:\n\t}" \
            :: "r"(_m), "r"(_p) : "memory"); \
    } } while (0)
#define BULK_G2S(dst, src, bytes, mbar) \
    asm volatile("cp.async.bulk.shared::cluster.global.mbarrier::complete_tx::bytes [%0], [%1], %2, [%3];" \
        :: "r"(dst), "l"(src), "r"((uint32_t)(bytes)), "r"(mbar) : "memory")

// ---------------- weight convert -> swizzled hi panels ----------------
__global__ __launch_bounds__(256) void wcvt_kernel(const float* __restrict__ src,
    __nv_bfloat16* __restrict__ dh, int O, int tiles)
{
    int i2 = blockIdx.x * 256 + threadIdx.x;
    if (i2 * 2 >= O * C) return;
    int o = (i2 * 2) / C, c = (i2 * 2) % C;
    float v0 = src[(size_t)o * C + c];
    float v1 = src[(size_t)o * C + c + 1];
    uint32_t ph = pk2(v0, v1);
    int panel = (c >> 6) * tiles + (o >> 7);
    int row = o & 127;
    uint32_t off = (uint32_t)panel * 16384u + (uint32_t)row * 128u
                 + ((uint32_t)((c & 63) * 2) ^ (uint32_t)((row & 7) * 16));
    *(uint32_t*)((char*)dh + off) = ph;
}

// ---------------- GroupNorm -> swizzled xn hi panels [b][kc][rt] ----------------
__global__ __launch_bounds__(256) void gn_t_kernel(
    const float* __restrict__ x, const float* __restrict__ gamma,
    const float* __restrict__ beta, __nv_bfloat16* __restrict__ xnh)
{
    const int CG = C / NG;
    const int GE = CG * NSP;
    int b = blockIdx.x / NG, g = blockIdx.x % NG;
    const float* xp = x + ((size_t)b * C + (size_t)g * CG) * NSP;
    int t = threadIdx.x;

    float s = 0.f, s2 = 0.f;
    for (int i = t; i < GE; i += 256) { float v = xp[i]; s += v; s2 += v * v; }
    __shared__ float rs[256], rs2[256];
    rs[t] = s; rs2[t] = s2;
    __syncthreads();
    for (int st = 128; st > 0; st >>= 1) {
        if (t < st) { rs[t] += rs[t + st]; rs2[t] += rs2[t + st]; }
        __syncthreads();
    }
    float mu  = rs[0] * (1.f / GE);
    float var = rs2[0] * (1.f / GE) - mu * mu;
    float inv = rsqrtf(var + 1e-5f);

    __shared__ float tile[8][32][33];
    int warp = t >> 5, lane = t & 31;
    for (int tt = warp; tt < 64; tt += 8) {
        int ci = tt >> 5, ni = tt & 31;
        for (int i = 0; i < 32; i++) {
            int c = ci * 32 + i;
            int cg2 = g * CG + c;
            float v = xp[(size_t)c * NSP + ni * 32 + lane];
            tile[warp][i][lane] = (v - mu) * inv * gamma[cg2] + beta[cg2];
        }
        __syncwarp();
        int col = ci * 32 + lane;
        for (int i = 0; i < 32; i++) {
            int n = ni * 32 + i;
            int rt = n >> 7, row = n & 127;
            size_t pb = (((size_t)b * 8 + g) * 8 + rt) * 16384;
            uint32_t off = (uint32_t)row * 128u
                         + ((uint32_t)(col * 2) ^ (uint32_t)((row & 7) * 16));
            *(__nv_bfloat16*)((char*)xnh + pb + off) = __float2bfloat16(tile[warp][lane][i]);
        }
        __syncwarp();
    }
}

// ---------------- GEMM mainloop: 256x128 CTA, 512 thr, single-term ----------------
#define GST_BH 32768u
#define GST_SZ 49152u

__device__ __forceinline__ void issue_chunk(uint32_t sdst, uint32_t mbar,
    const char* Ah, size_t aoff, const char* Bh, size_t boff)
{
    MBAR_EXPECT(mbar, 49152u);
    BULK_G2S(sdst,          Ah + aoff, 32768u, mbar);
    BULK_G2S(sdst + GST_BH, Bh + boff, 16384u, mbar);
}

__device__ __forceinline__ void gemm_mainloop(uint32_t sbase, uint32_t mb0, uint32_t mb1,
    const char* Ah, int rtA, int RT,
    const char* Bh, int ntB, int NT,
    int nk, float (&acc)[2][8][4])
{
    const int tid = threadIdx.x, lane = tid & 31, wid = tid >> 5;
    const int warp_m = (wid >> 1) * 32;
    const int warp_n = (wid & 1) * 64;
    const int lr = (lane & 7) + 8 * ((lane >> 3) & 1);
    const int lc = 16 * (lane >> 4);
    const uint32_t rx = (uint32_t)(lr & 7) * 16u;
    uint32_t kx[4];
#pragma unroll
    for (int k = 0; k < 4; k++)
        kx[k] = ((32u * k) ^ (rx & 0x60u)) + ((uint32_t)lc ^ (rx & 0x10u));

    uint32_t rA[2], rB[4];
#pragma unroll
    for (int t = 0; t < 2; t++) {
        int full = warp_m + t * 16 + lr;
        rA[t] = (uint32_t)((full >> 7) * 16384 + (full & 127) * 128);
    }
#pragma unroll
    for (int t = 0; t < 4; t++)
        rB[t] = (uint32_t)(warp_n + t * 16 + lr) * 128u;

    if (tid == 0) {
        issue_chunk(sbase, mb0, Ah, (size_t)(0 * RT + rtA) * 16384,
                    Bh, (size_t)(0 * NT + ntB) * 16384);
        if (nk > 1)
            issue_chunk(sbase + GST_SZ, mb1, Ah, (size_t)(1 * RT + rtA) * 16384,
                        Bh, (size_t)(1 * NT + ntB) * 16384);
    }

    for (int i = 0; i < nk; i++) {
        MBAR_WAIT((i & 1) ? mb1 : mb0, (uint32_t)((i >> 1) & 1));

        uint32_t bufA = sbase + (uint32_t)(i & 1) * GST_SZ;
        uint32_t bufB = bufA + GST_BH;
#pragma unroll
        for (int kk = 0; kk < 4; kk++) {
            uint32_t kof = kx[kk];
            uint32_t ah0[4], ah1[4];
            ldsm4(ah0, bufA + rA[0] + kof);
            ldsm4(ah1, bufA + rA[1] + kof);
#pragma unroll
            for (int nt = 0; nt < 4; nt++) {
                uint32_t bh_[4];
                ldsm4(bh_, bufB + rB[nt] + kof);
                int j0 = nt * 2, j1 = nt * 2 + 1;
                mma16816(acc[0][j0], ah0, bh_[0], bh_[2]);
                mma16816(acc[1][j0], ah1, bh_[0], bh_[2]);
                mma16816(acc[0][j1], ah0, bh_[1], bh_[3]);
                mma16816(acc[1][j1], ah1, bh_[1], bh_[3]);
            }
        }
        __syncthreads();
        if (tid == 0 && i + 2 < nk)
            issue_chunk(sbase + (uint32_t)(i & 1) * GST_SZ, (i & 1) ? mb1 : mb0,
                        Ah, (size_t)((i + 2) * RT + rtA) * 16384,
                        Bh, (size_t)((i + 2) * NT + ntB) * 16384);
    }
}

// ---------------- QKV GEMM with fused Q/K/V panel epilogues ----------------
__global__ __launch_bounds__(512) void gemm_qkv(
    const __nv_bfloat16* __restrict__ xnh,
    const __nv_bfloat16* __restrict__ qwh,
    const float* __restrict__ bias,
    __nv_bfloat16* __restrict__ Qh,
    __nv_bfloat16* __restrict__ Kh, __nv_bfloat16* __restrict__ Vh)
{
    extern __shared__ char dsm[];
    char* base = (char*)((((uintptr_t)dsm) + 1023) & ~(uintptr_t)1023);
    const uint32_t sbase = smem_u32(base);
    __shared__ __align__(8) unsigned long long smb[2];
    uint32_t mb0 = smem_u32(&smb[0]), mb1 = smem_u32(&smb[1]);
    const int tid = threadIdx.x, lane = tid & 31, wid = tid >> 5;
    const int bb = blockIdx.z;
    const int nb = blockIdx.x;
    const int m0 = blockIdx.y * 256, n0 = nb * 128;

    if (tid == 0) { MBAR_INIT(mb0, 1); MBAR_INIT(mb1, 1); }
    __syncthreads();

    float acc[2][8][4] = {};
    gemm_mainloop(sbase, mb0, mb1,
        (const char*)xnh + (size_t)bb * NSP * C * 2, m0 >> 7, 8,
        (const char*)qwh, nb, 12, 8, acc);

    const int warp_m = (wid >> 1) * 32;
    const int warp_n = (wid & 1) * 64;
    const int er = lane >> 2, ec = (lane & 3) * 2;

    if (nb < 4) {
        int h = nb;
#pragma unroll
        for (int mt = 0; mt < 2; mt++)
#pragma unroll
        for (int half = 0; half < 2; half++) {
            int m = m0 + warp_m + mt * 16 + er + half * 8;
            int qb = m >> 7, row = m & 127;
            size_t pb = (((size_t)(bb * NH + h) * 8 + qb) * 2) * 16384;
            uint32_t rowoff = (uint32_t)row * 128u;
            uint32_t rsw = (uint32_t)((row & 7) * 16);
#pragma unroll
            for (int j = 0; j < 8; j++) {
                int n = n0 + warp_n + j * 8 + ec;
                int cl = n & 127;
                float v0 = (acc[mt][j][half * 2 + 0] + bias[n])     * SC2;
                float v1 = (acc[mt][j][half * 2 + 1] + bias[n + 1]) * SC2;
                size_t off = pb + (size_t)(cl >> 6) * 16384 + rowoff
                           + (((uint32_t)((cl & 63) * 2)) ^ rsw);
                *(uint32_t*)((char*)Qh + off) = pk2(v0, v1);
            }
        }
    } else if (nb < 8) {
        int h = nb - 4;
        size_t pbase = (size_t)(bb * NH + h) * 8 * 32768;
#pragma unroll
        for (int mt = 0; mt < 2; mt++)
#pragma unroll
        for (int half = 0; half < 2; half++) {
            int m = m0 + warp_m + mt * 16 + er + half * 8;
            int mc = m >> 7, row = m & 127;
            size_t cb = pbase + (size_t)mc * 32768;
            uint32_t rowoff = (uint32_t)row * 128u;
            uint32_t rsw = (uint32_t)((row & 7) * 16);
#pragma unroll
            for (int j = 0; j < 8; j++) {
                int dloc = warp_n + j * 8 + ec;
                int n = n0 + dloc;
                float v0 = acc[mt][j][half * 2 + 0] + bias[n];
                float v1 = acc[mt][j][half * 2 + 1] + bias[n + 1];
                size_t off = cb + (size_t)(dloc >> 6) * 16384 + rowoff
                           + (((uint32_t)((dloc & 63) * 2)) ^ rsw);
                *(uint32_t*)((char*)Kh + off) = pk2(v0, v1);
            }
        }
    } else {
        int h = nb - 8;
        float* vt = (float*)base;   // 256x129 fp32 = 132096 B (DSM sized for this)
#pragma unroll
        for (int mt = 0; mt < 2; mt++)
#pragma unroll
        for (int half = 0; half < 2; half++) {
            int mloc = warp_m + mt * 16 + er + half * 8;
#pragma unroll
            for (int j = 0; j < 8; j++) {
                int dloc = warp_n + j * 8 + ec;
                int n = n0 + dloc;
                vt[mloc * 129 + dloc]     = acc[mt][j][half * 2 + 0] + bias[n];
                vt[mloc * 129 + dloc + 1] = acc[mt][j][half * 2 + 1] + bias[n + 1];
            }
        }
        __syncthreads();
        size_t pbase = (size_t)(bb * NH + h) * 8 * 32768;
        for (int idx = tid; idx < 16384; idx += 512) {
            int cLoc = idx >> 13;
            int rem = idx & 8191;
            int o2 = rem * 2;
            int p = o2 >> 13, rem2 = o2 & 8191;
            int d = rem2 >> 6, kvc = rem2 & 63;
            int srow = cLoc * 128 + p * 64 + kvc;
            float v0 = vt[srow * 129 + d];
            float v1 = vt[(srow + 1) * 129 + d];
            size_t off = pbase + (size_t)((m0 >> 7) + cLoc) * 32768
                       + (size_t)p * 16384 + (uint32_t)d * 128u
                       + (((uint32_t)(kvc * 2)) ^ (uint32_t)((d & 7) * 16));
            *(uint32_t*)((char*)Vh + off) = pk2(v0, v1);
        }
    }
}

// ---------------- generic GEMM (proj) ----------------
__global__ __launch_bounds__(512) void gemm_bf(
    const __nv_bfloat16* __restrict__ Ah, int RT,
    const __nv_bfloat16* __restrict__ Bh, int NT, long long sBb,
    float* __restrict__ Cm, long long ldc, long long sCb,
    const float* __restrict__ bias_m,
    const float* __restrict__ res, long long ldr, long long sRb)
{
    extern __shared__ char dsm[];
    char* base = (char*)((((uintptr_t)dsm) + 1023) & ~(uintptr_t)1023);
    const uint32_t sbase = smem_u32(base);
    __shared__ __align__(8) unsigned long long smb[2];
    uint32_t mb0 = smem_u32(&smb[0]), mb1 = smem_u32(&smb[1]);
    const int tid = threadIdx.x, lane = tid & 31, wid = tid >> 5;
    const int bb = blockIdx.z;
    const int m0 = blockIdx.y * 256, n0 = blockIdx.x * 128;

    if (tid == 0) { MBAR_INIT(mb0, 1); MBAR_INIT(mb1, 1); }
    __syncthreads();

    float acc[2][8][4] = {};
    gemm_mainloop(sbase, mb0, mb1,
        (const char*)Ah, m0 >> 7, RT,
        (const char*)Bh + (size_t)bb * sBb, n0 >> 7, NT, 8, acc);

    Cm += (size_t)bb * sCb;
    if (res) res += (size_t)bb * sRb;
    const int warp_m = (wid >> 1) * 32, warp_n = (wid & 1) * 64;
    const int er = lane >> 2, ec = (lane & 3) * 2;
#pragma unroll
    for (int mt = 0; mt < 2; mt++)
#pragma unroll
    for (int half = 0; half < 2; half++) {
        int m = m0 + warp_m + mt * 16 + er + half * 8;
        float bm_ = bias_m ? bias_m[m] : 0.f;
#pragma unroll
        for (int j = 0; j < 8; j++) {
            int n = n0 + warp_n + j * 8 + ec;
            float v0 = acc[mt][j][half * 2 + 0] + bm_;
            float v1 = acc[mt][j][half * 2 + 1] + bm_;
            if (res) { const float* rp = res + (size_t)m * ldr + n; v0 += rp[0]; v1 += rp[1]; }
            *(float2*)&Cm[(size_t)m * ldc + n] = make_float2(v0, v1);
        }
    }
}

// ---------------- flash attention: bf16 single-term, K+V double-buffered ----------------
#define FQB  0u
#define FKB  32768u
#define FVB  98304u

__global__ __launch_bounds__(256) void flash_kernel(
    const __nv_bfloat16* __restrict__ Qh,
    const __nv_bfloat16* __restrict__ Kh, const __nv_bfloat16* __restrict__ Vh,
    __nv_bfloat16* __restrict__ atth)
{
    extern __shared__ char dsm[];
    char* base = (char*)((((uintptr_t)dsm) + 1023) & ~(uintptr_t)1023);
    const uint32_t sb = smem_u32(base);
    __shared__ __align__(8) unsigned long long fmb[5];
    uint32_t mbQ  = smem_u32(&fmb[0]);
    uint32_t mbK0 = smem_u32(&fmb[1]), mbK1 = smem_u32(&fmb[2]);
    uint32_t mbV0 = smem_u32(&fmb[3]), mbV1 = smem_u32(&fmb[4]);
    const int tid = threadIdx.x, lane = tid & 31, wid = tid >> 5;
    const int qb = blockIdx.x;
    const int z = blockIdx.y;
    const int b = z >> 2, h = z & 3;

    const char* KhP = (const char*)Kh + (size_t)z * 8 * 32768;
    const char* VhP = (const char*)Vh + (size_t)z * 8 * 32768;
    const char* QhP = (const char*)Qh + (size_t)((b * NH + h) * 8 + qb) * 32768;

    if (tid == 0) {
        MBAR_INIT(mbQ, 1); MBAR_INIT(mbK0, 1); MBAR_INIT(mbK1, 1);
        MBAR_INIT(mbV0, 1); MBAR_INIT(mbV1, 1);
    }
    __syncthreads();
    if (tid == 0) {
        MBAR_EXPECT(mbQ, 32768u);
        BULK_G2S(sb + FQB, QhP, 32768u, mbQ);
        MBAR_EXPECT(mbK0, 32768u);
        BULK_G2S(sb + FKB,          KhP, 32768u, mbK0);
        MBAR_EXPECT(mbK1, 32768u);
        BULK_G2S(sb + FKB + 32768u, KhP + 32768, 32768u, mbK1);
        MBAR_EXPECT(mbV0, 32768u);
        BULK_G2S(sb + FVB,          VhP, 32768u, mbV0);
        MBAR_EXPECT(mbV1, 32768u);
        BULK_G2S(sb + FVB + 32768u, VhP + 32768, 32768u, mbV1);
    }

    const int lr = (lane & 7) + 8 * ((lane >> 3) & 1);
    const int lc = 16 * (lane >> 4);
    const uint32_t rx = (uint32_t)(lr & 7) * 16u;
    uint32_t kx[4];
#pragma unroll
    for (int k = 0; k < 4; k++)
        kx[k] = ((32u * k) ^ (rx & 0x60u)) + ((uint32_t)lc ^ (rx & 0x10u));
    const uint32_t qoff = (uint32_t)(16 * wid + lr) * 128u;

    MBAR_WAIT(mbQ, 0u);

    float accO[16][4] = {};
    float M0 = -1e30f, M1 = -1e30f, L0 = 0.f, L1 = 0.f;

    for (int c = 0; c < 8; c++) {
        float accS[16][4] = {};
        uint32_t kb = sb + FKB + (uint32_t)(c & 1) * 32768u;
        MBAR_WAIT((c & 1) ? mbK1 : mbK0, (uint32_t)((c >> 1) & 1));
        // ---- QK ----
#pragma unroll
        for (int p = 0; p < 2; p++) {
#pragma unroll
            for (int kk = 0; kk < 4; kk++) {
                uint32_t kof = kx[kk];
                uint32_t ah[4];
                ldsm4(ah, sb + FQB + p * 16384 + qoff + kof);
#pragma unroll
                for (int nt = 0; nt < 8; nt++) {
                    uint32_t bh_[4];
                    ldsm4(bh_, kb + p * 16384 + (uint32_t)(nt * 16 + lr) * 128u + kof);
                    mma16816(accS[2*nt],   ah, bh_[0], bh_[2]);
                    mma16816(accS[2*nt+1], ah, bh_[1], bh_[3]);
                }
            }
        }
        __syncthreads();
        if (tid == 0 && c + 2 < 8) {
            uint32_t mk = (c & 1) ? mbK1 : mbK0;
            MBAR_EXPECT(mk, 32768u);
            BULK_G2S(kb, KhP + (size_t)(c + 2) * 32768, 32768u, mk);
        }
        // ---- online softmax (base-2) ----
        float m0 = -1e30f, m1 = -1e30f;
#pragma unroll
        for (int j = 0; j < 16; j++) {
            m0 = fmaxf(m0, fmaxf(accS[j][0], accS[j][1]));
            m1 = fmaxf(m1, fmaxf(accS[j][2], accS[j][3]));
        }
        m0 = fmaxf(m0, __shfl_xor_sync(0xffffffffu, m0, 1));
        m0 = fmaxf(m0, __shfl_xor_sync(0xffffffffu, m0, 2));
        m1 = fmaxf(m1, __shfl_xor_sync(0xffffffffu, m1, 1));
        m1 = fmaxf(m1, __shfl_xor_sync(0xffffffffu, m1, 2));
        float nM0 = fmaxf(M0, m0), nM1 = fmaxf(M1, m1);
        float a0 = exp2f(M0 - nM0), a1 = exp2f(M1 - nM1);
        M0 = nM0; M1 = nM1;
        float s0 = 0.f, s1 = 0.f;
#pragma unroll
        for (int j = 0; j < 16; j++) {
            accS[j][0] = exp2f(accS[j][0] - M0);
            accS[j][1] = exp2f(accS[j][1] - M0);
            accS[j][2] = exp2f(accS[j][2] - M1);
            accS[j][3] = exp2f(accS[j][3] - M1);
            s0 += accS[j][0] + accS[j][1];
            s1 += accS[j][2] + accS[j][3];
        }
        s0 += __shfl_xor_sync(0xffffffffu, s0, 1);
        s0 += __shfl_xor_sync(0xffffffffu, s0, 2);
        s1 += __shfl_xor_sync(0xffffffffu, s1, 1);
        s1 += __shfl_xor_sync(0xffffffffu, s1, 2);
        L0 = L0 * a0 + s0;
        L1 = L1 * a1 + s1;
#pragma unroll
        for (int j = 0; j < 16; j++) {
            accO[j][0] *= a0; accO[j][1] *= a0;
            accO[j][2] *= a1; accO[j][3] *= a1;
        }
        uint32_t vb = sb + FVB + (uint32_t)(c & 1) * 32768u;
        MBAR_WAIT((c & 1) ? mbV1 : mbV0, (uint32_t)((c >> 1) & 1));
        // ---- PV ----
#pragma unroll
        for (int p = 0; p < 2; p++) {
#pragma unroll
            for (int kk = 0; kk < 4; kk++) {
                int kt = p * 4 + kk;
                uint32_t kof = kx[kk];
                uint32_t phi[4];
                {
                    const float* e0 = accS[2*kt];
                    const float* e1 = accS[2*kt+1];
                    phi[0] = pk2(e0[0], e0[1]);
                    phi[1] = pk2(e0[2], e0[3]);
                    phi[2] = pk2(e1[0], e1[1]);
                    phi[3] = pk2(e1[2], e1[3]);
                }
#pragma unroll
                for (int nt = 0; nt < 8; nt++) {
                    uint32_t vh_[4];
                    ldsm4(vh_, vb + p * 16384 + (uint32_t)(nt * 16 + lr) * 128u + kof);
                    mma16816(accO[2*nt],   phi, vh_[0], vh_[2]);
                    mma16816(accO[2*nt+1], phi, vh_[1], vh_[3]);
                }
            }
        }
        __syncthreads();
        if (tid == 0 && c + 2 < 8) {
            uint32_t mv = (c & 1) ? mbV1 : mbV0;
            MBAR_EXPECT(mv, 32768u);
            BULK_G2S(vb, VhP + (size_t)(c + 2) * 32768, 32768u, mv);
        }
    }

    // epilogue -> att panels [b][kc][nt=qb]
    float i0 = 1.f / L0, i1 = 1.f / L1;
    int r1 = 16 * wid + (lane >> 2);
    int ec = (lane & 3) * 2;
    char* ath = (char*)atth + (size_t)b * NSP * C * 2;
#pragma unroll
    for (int j = 0; j < 16; j++) {
        int cf = j * 8 + ec;
        int kc = h * 2 + (cf >> 6);
        uint32_t cb = ((uint32_t)(cf & 63)) * 2u;
        size_t pb = (size_t)(kc * 8 + qb) * 16384;
        {
            size_t off = pb + (uint32_t)r1 * 128u + (cb ^ (uint32_t)((r1 & 7) * 16));
            *(uint32_t*)(ath + off) = pk2(accO[j][0] * i0, accO[j][1] * i0);
        }
        {
            int r2 = r1 + 8;
            size_t off = pb + (uint32_t)r2 * 128u + (cb ^ (uint32_t)((r2 & 7) * 16));
            *(uint32_t*)(ath + off) = pk2(accO[j][2] * i1, accO[j][3] * i1);
        }
    }
}

// ---------------- launch ----------------
extern "C" void kernel_launch(void* const* d_in, const int* in_sizes, int n_in,
                              void* d_out, int out_size)
{
    const float* x      = (const float*)d_in[0];
    const float* gamma  = (const float*)d_in[1];
    const float* beta   = (const float*)d_in[2];
    const float* qkv_w  = (const float*)d_in[3];
    const float* qkv_b  = (const float*)d_in[4];
    const float* proj_w = (const float*)d_in[5];
    const float* proj_b = (const float*)d_in[6];
    float* out = (float*)d_out;

    __nv_bfloat16 *xnh, *qwh, *pwh, *Qh, *atth, *Kh, *Vh;
    cudaGetSymbolAddress((void**)&xnh,  g_xnh);
    cudaGetSymbolAddress((void**)&qwh,  g_qwh);
    cudaGetSymbolAddress((void**)&pwh,  g_pwh);
    cudaGetSymbolAddress((void**)&Qh,   g_Qh);
    cudaGetSymbolAddress((void**)&atth, g_atth);
    cudaGetSymbolAddress((void**)&Kh,   g_Kh);
    cudaGetSymbolAddress((void**)&Vh,   g_Vh);

    // gemm_qkv smem: max(2*49152 mainloop, 256*129*4 V staging) + 1024 align
    const int DSM  = 1024 + 132096;      // 133120
    const int PDSM = 1024 + 2 * 49152;   // 99328 (proj has no V staging)
    const int FDSM = 1024 + 163840;      // 164864
    cudaFuncSetAttribute(gemm_qkv,     cudaFuncAttributeMaxDynamicSharedMemorySize, DSM);
    cudaFuncSetAttribute(gemm_bf,      cudaFuncAttributeMaxDynamicSharedMemorySize, PDSM);
    cudaFuncSetAttribute(flash_kernel, cudaFuncAttributeMaxDynamicSharedMemorySize, FDSM);

    // 0) weight hi panels
    wcvt_kernel<<<1536, 256>>>(qkv_w, qwh, 3 * C, 12);
    wcvt_kernel<<<512,  256>>>(proj_w, pwh, C, 4);

    // 1) GroupNorm -> xn hi panels
    gn_t_kernel<<<B * NG, 256>>>(x, gamma, beta, xnh);

    // 2) QKV GEMM -> Q/K/V hi panels
    gemm_qkv<<<dim3(12, 4, B), 512, DSM>>>(xnh, qwh, qkv_b, Qh, Kh, Vh);

    // 3) fused attention -> att hi panels
    flash_kernel<<<dim3(8, B * NH), 256, FDSM>>>(Qh, Kh, Vh, atth);

    // 4) proj + bias + residual: out[b][c][n]
    gemm_bf<<<dim3(8, 2, B), 512, PDSM>>>(
        pwh, 4,
        atth, 8, (long long)NSP * C * 2,
        out, NSP, (long long)C * NSP,
        proj_b, x, NSP, (long long)C * NSP);
}